// round 1
// baseline (speedup 1.0000x reference)
#include <cuda_runtime.h>
#include <cuda_bf16.h>
#include <math.h>

// Problem dimensions (fixed by the reference)
#define BB    4
#define SS    2048
#define DM    1024
#define HH    16
#define DK    64
#define DFF   4096
#define MROWS (BB*SS)          // 8192
#define LN_EPS 1e-5f

// ---------------------------------------------------------------------------
// Scratch (device globals; no allocations allowed)
// ---------------------------------------------------------------------------
__device__ float g_h [MROWS*DM];    // ln1 output / ln2 output (reused)
__device__ float g_q [MROWS*DM];
__device__ float g_k [MROWS*DM];
__device__ float g_v [MROWS*DM];
__device__ float g_o [MROWS*DM];    // attention output
__device__ float g_x1[MROWS*DM];    // residual after attention
__device__ float g_ff[MROWS*DFF];   // FFN hidden

// ---------------------------------------------------------------------------
// LayerNorm: one block per row (1024 elems), 256 threads, float4 per thread
// ---------------------------------------------------------------------------
__global__ __launch_bounds__(256) void ln_kernel(
    const float* __restrict__ X, const float* __restrict__ gamma,
    const float* __restrict__ beta, float* __restrict__ out)
{
    const int row = blockIdx.x;
    const int t   = threadIdx.x;                 // 0..255
    const float4 v = ((const float4*)(X + (size_t)row*DM))[t];

    float s  = v.x + v.y + v.z + v.w;
    float ss = v.x*v.x + v.y*v.y + v.z*v.z + v.w*v.w;

    #pragma unroll
    for (int o = 16; o > 0; o >>= 1) {
        s  += __shfl_xor_sync(0xffffffffu, s,  o);
        ss += __shfl_xor_sync(0xffffffffu, ss, o);
    }
    __shared__ float sh_s[8], sh_ss[8];
    const int w = t >> 5, lane = t & 31;
    if (lane == 0) { sh_s[w] = s; sh_ss[w] = ss; }
    __syncthreads();
    if (w == 0) {
        s  = (lane < 8) ? sh_s[lane]  : 0.f;
        ss = (lane < 8) ? sh_ss[lane] : 0.f;
        #pragma unroll
        for (int o = 4; o > 0; o >>= 1) {
            s  += __shfl_xor_sync(0xffffffffu, s,  o);
            ss += __shfl_xor_sync(0xffffffffu, ss, o);
        }
        if (lane == 0) { sh_s[0] = s; sh_ss[0] = ss; }
    }
    __syncthreads();
    s = sh_s[0]; ss = sh_ss[0];

    const float mu   = s * (1.0f / DM);
    const float var  = ss * (1.0f / DM) - mu*mu;
    const float rstd = rsqrtf(var + LN_EPS);

    const float4 g4 = ((const float4*)gamma)[t];
    const float4 b4 = ((const float4*)beta)[t];
    float4 o4;
    o4.x = (v.x - mu)*rstd*g4.x + b4.x;
    o4.y = (v.y - mu)*rstd*g4.y + b4.y;
    o4.z = (v.z - mu)*rstd*g4.z + b4.z;
    o4.w = (v.w - mu)*rstd*g4.w + b4.w;
    ((float4*)(out + (size_t)row*DM))[t] = o4;
}

// ---------------------------------------------------------------------------
// SGEMM: C[M,N] = A[M,K] @ B[K,N] + bias[N]  (+ optional ReLU, + optional res)
// 128x128 block tile, BK=16, 8x8 per thread, 256 threads. All dims divisible.
// ---------------------------------------------------------------------------
template<bool RELU, bool RES>
__global__ __launch_bounds__(256) void sgemm_kernel(
    const float* __restrict__ A, const float* __restrict__ B,
    const float* __restrict__ bias, const float* __restrict__ res,
    float* __restrict__ C, int M, int N, int K)
{
    constexpr int BM = 128, BN = 128, BK = 16, TM = 8, TN = 8;
    __shared__ float As[BK][BM];   // transposed A tile
    __shared__ float Bs[BK][BN];

    const int bx = blockIdx.x, by = blockIdx.y;
    const int tid = threadIdx.x;
    const int tx = tid & 15, ty = tid >> 4;

    const float* Ab = A + (size_t)by * BM * K;
    const float* Bb = B + (size_t)bx * BN;

    float acc[TM][TN];
    #pragma unroll
    for (int i = 0; i < TM; i++)
        #pragma unroll
        for (int j = 0; j < TN; j++) acc[i][j] = 0.f;

    for (int kt = 0; kt < K; kt += BK) {
        // Load A tile (128x16) -> As transposed.  512 float4 slots / 256 thr.
        #pragma unroll
        for (int i = 0; i < 2; i++) {
            int s  = tid + i*256;
            int r  = s >> 2;            // 0..127
            int c4 = s & 3;             // 0..3
            float4 a4 = *(const float4*)(Ab + (size_t)r*K + kt + c4*4);
            As[c4*4+0][r] = a4.x;
            As[c4*4+1][r] = a4.y;
            As[c4*4+2][r] = a4.z;
            As[c4*4+3][r] = a4.w;
        }
        // Load B tile (16x128).  512 float4 slots / 256 thr. Fully coalesced.
        #pragma unroll
        for (int i = 0; i < 2; i++) {
            int s  = tid + i*256;
            int r  = s >> 5;            // 0..15
            int c4 = s & 31;            // 0..31
            *(float4*)&Bs[r][c4*4] =
                *(const float4*)(Bb + (size_t)(kt + r)*N + c4*4);
        }
        __syncthreads();

        #pragma unroll
        for (int k = 0; k < BK; k++) {
            float a[TM], b[TN];
            *(float4*)&a[0] = *(float4*)&As[k][ty*TM];
            *(float4*)&a[4] = *(float4*)&As[k][ty*TM + 4];
            *(float4*)&b[0] = *(float4*)&Bs[k][tx*TN];
            *(float4*)&b[4] = *(float4*)&Bs[k][tx*TN + 4];
            #pragma unroll
            for (int i = 0; i < TM; i++)
                #pragma unroll
                for (int j = 0; j < TN; j++)
                    acc[i][j] += a[i]*b[j];
        }
        __syncthreads();
    }

    // Epilogue
    #pragma unroll
    for (int i = 0; i < TM; i++) {
        const int r = by*BM + ty*TM + i;
        #pragma unroll
        for (int j = 0; j < TN; j += 4) {
            const int c = bx*BN + tx*TN + j;
            const float4 bi = *(const float4*)(bias + c);
            float4 o4;
            o4.x = acc[i][j+0] + bi.x;
            o4.y = acc[i][j+1] + bi.y;
            o4.z = acc[i][j+2] + bi.z;
            o4.w = acc[i][j+3] + bi.w;
            if (RELU) {
                o4.x = fmaxf(o4.x, 0.f); o4.y = fmaxf(o4.y, 0.f);
                o4.z = fmaxf(o4.z, 0.f); o4.w = fmaxf(o4.w, 0.f);
            }
            if (RES) {
                const float4 r4 = *(const float4*)(res + (size_t)r*N + c);
                o4.x += r4.x; o4.y += r4.y; o4.z += r4.z; o4.w += r4.w;
            }
            *(float4*)(C + (size_t)r*N + c) = o4;
        }
    }
}

// ---------------------------------------------------------------------------
// Causal flash attention, fp32, d_k=64.
// Grid: (S/64, B*H). Block: 64 threads, one query per thread.
// q[64] and acc[64] live in registers; K/V 64x64 tiles in smem (32 KB).
// ---------------------------------------------------------------------------
__global__ __launch_bounds__(64) void attn_kernel(
    const float* __restrict__ Q, const float* __restrict__ K,
    const float* __restrict__ V, float* __restrict__ O)
{
    const int qt = blockIdx.x;           // query tile
    const int bh = blockIdx.y;
    const int b  = bh >> 4;
    const int h  = bh & 15;
    const int t  = threadIdx.x;          // 0..63
    const int qg = qt*64 + t;            // global query index within sequence

    __shared__ float Ks[64][64];
    __shared__ float Vs[64][64];

    // Load this thread's query row into registers
    const float* qp = Q + ((size_t)(b*SS + qg))*DM + h*DK;
    float q[DK];
    #pragma unroll
    for (int k = 0; k < DK; k += 4) {
        const float4 v4 = *(const float4*)(qp + k);
        q[k] = v4.x; q[k+1] = v4.y; q[k+2] = v4.z; q[k+3] = v4.w;
    }

    float acc[DK];
    #pragma unroll
    for (int d = 0; d < DK; d++) acc[d] = 0.f;
    float m = -INFINITY, l = 0.f;

    const float scale = 0.125f;          // 1/sqrt(64)

    for (int kt = 0; kt <= qt; kt++) {
        __syncthreads();
        // Cooperative coalesced load of K/V 64x64 tiles:
        // 1024 float4 slots; idx = i*64 + t -> 16 consecutive threads per row.
        const float* kb = K + ((size_t)(b*SS + kt*64))*DM + h*DK;
        const float* vb = V + ((size_t)(b*SS + kt*64))*DM + h*DK;
        #pragma unroll
        for (int i = 0; i < 16; i++) {
            const int idx = i*64 + t;
            const int r = idx >> 4;
            const int c = (idx & 15) << 2;
            *(float4*)&Ks[r][c] = *(const float4*)(kb + (size_t)r*DM + c);
            *(float4*)&Vs[r][c] = *(const float4*)(vb + (size_t)r*DM + c);
        }
        __syncthreads();

        const int jmax = (kt == qt) ? (t + 1) : 64;   // causal bound
        for (int j = 0; j < jmax; j++) {
            float s = 0.f;
            #pragma unroll
            for (int k = 0; k < DK; k += 4) {
                const float4 kv = *(const float4*)&Ks[j][k];
                s += q[k]*kv.x + q[k+1]*kv.y + q[k+2]*kv.z + q[k+3]*kv.w;
            }
            s *= scale;

            const float mn = fmaxf(m, s);
            if (mn > m) {
                const float corr = __expf(m - mn);   // 0 on first key
                l *= corr;
                #pragma unroll
                for (int d = 0; d < DK; d++) acc[d] *= corr;
                m = mn;
            }
            const float p = __expf(s - m);
            l += p;
            #pragma unroll
            for (int d = 0; d < DK; d += 4) {
                const float4 vv = *(const float4*)&Vs[j][d];
                acc[d]   += p*vv.x; acc[d+1] += p*vv.y;
                acc[d+2] += p*vv.z; acc[d+3] += p*vv.w;
            }
        }
    }

    const float inv = 1.0f / l;
    float* op = O + ((size_t)(b*SS + qg))*DM + h*DK;
    #pragma unroll
    for (int d = 0; d < DK; d += 4) {
        float4 o4;
        o4.x = acc[d]*inv;   o4.y = acc[d+1]*inv;
        o4.z = acc[d+2]*inv; o4.w = acc[d+3]*inv;
        *(float4*)(op + d) = o4;
    }
}

// ---------------------------------------------------------------------------
// Launch
// ---------------------------------------------------------------------------
extern "C" void kernel_launch(void* const* d_in, const int* in_sizes, int n_in,
                              void* d_out, int out_size)
{
    const float* x   = (const float*)d_in[0];
    const float* Wq  = (const float*)d_in[1];
    const float* bq  = (const float*)d_in[2];
    const float* Wk  = (const float*)d_in[3];
    const float* bk  = (const float*)d_in[4];
    const float* Wv  = (const float*)d_in[5];
    const float* bv  = (const float*)d_in[6];
    const float* Wo  = (const float*)d_in[7];
    const float* bo  = (const float*)d_in[8];
    const float* W1  = (const float*)d_in[9];
    const float* b1  = (const float*)d_in[10];
    const float* W2  = (const float*)d_in[11];
    const float* b2  = (const float*)d_in[12];
    const float* g1  = (const float*)d_in[13];
    const float* be1 = (const float*)d_in[14];
    const float* g2  = (const float*)d_in[15];
    const float* be2 = (const float*)d_in[16];
    float* out = (float*)d_out;

    float *p_h, *p_q, *p_k, *p_v, *p_o, *p_x1, *p_ff;
    cudaGetSymbolAddress((void**)&p_h,  g_h);
    cudaGetSymbolAddress((void**)&p_q,  g_q);
    cudaGetSymbolAddress((void**)&p_k,  g_k);
    cudaGetSymbolAddress((void**)&p_v,  g_v);
    cudaGetSymbolAddress((void**)&p_o,  g_o);
    cudaGetSymbolAddress((void**)&p_x1, g_x1);
    cudaGetSymbolAddress((void**)&p_ff, g_ff);

    const dim3 blk(256);
    const dim3 gD (DM/128,  MROWS/128);   // N=1024 GEMMs
    const dim3 gF (DFF/128, MROWS/128);   // N=4096 GEMM

    // 1. ln1(x) -> h
    ln_kernel<<<MROWS, 256>>>(x, g1, be1, p_h);
    // 2-4. Q/K/V projections
    sgemm_kernel<false,false><<<gD, blk>>>(p_h, Wq, bq, nullptr, p_q, MROWS, DM, DM);
    sgemm_kernel<false,false><<<gD, blk>>>(p_h, Wk, bk, nullptr, p_k, MROWS, DM, DM);
    sgemm_kernel<false,false><<<gD, blk>>>(p_h, Wv, bv, nullptr, p_v, MROWS, DM, DM);
    // 5. causal attention
    attn_kernel<<<dim3(SS/64, BB*HH), 64>>>(p_q, p_k, p_v, p_o);
    // 6. output projection + residual(x) -> x1
    sgemm_kernel<false,true><<<gD, blk>>>(p_o, Wo, bo, x, p_x1, MROWS, DM, DM);
    // 7. ln2(x1) -> h (reuse)
    ln_kernel<<<MROWS, 256>>>(p_x1, g2, be2, p_h);
    // 8. FFN up + ReLU
    sgemm_kernel<true,false><<<gF, blk>>>(p_h, W1, b1, nullptr, p_ff, MROWS, DFF, DM);
    // 9. FFN down + residual(x1) -> out
    sgemm_kernel<false,true><<<gD, blk>>>(p_ff, W2, b2, p_x1, out, MROWS, DM, DFF);
}

// round 3
// speedup vs baseline: 3.1490x; 3.1490x over previous
#include <cuda_runtime.h>
#include <cuda_bf16.h>
#include <math.h>
#include <stdint.h>

// Problem dimensions (fixed by the reference)
#define BB    4
#define SS    2048
#define DM    1024
#define HH    16
#define DK    64
#define DFF   4096
#define MROWS (BB*SS)          // 8192
#define LN_EPS 1e-5f

// ---------------------------------------------------------------------------
// Scratch (device globals; no allocations allowed)
// ---------------------------------------------------------------------------
__device__ float g_h  [MROWS*DM];    // ln1 / ln2 output (tf32-rounded)
__device__ float g_q  [MROWS*DM];
__device__ float g_k  [MROWS*DM];
__device__ float g_v  [MROWS*DM];
__device__ float g_o  [MROWS*DM];    // attention output (tf32-rounded)
__device__ float g_x1 [MROWS*DM];    // residual after attention
__device__ float g_ff [MROWS*DFF];   // FFN hidden (tf32-rounded)
__device__ float g_wqt[DM*DM];       // transposed + tf32-rounded weights [N,K]
__device__ float g_wkt[DM*DM];
__device__ float g_wvt[DM*DM];
__device__ float g_wot[DM*DM];
__device__ float g_w1t[DFF*DM];      // [4096,1024]
__device__ float g_w2t[DM*DFF];      // [1024,4096]

// ---------------------------------------------------------------------------
// Helpers
// ---------------------------------------------------------------------------
__device__ __forceinline__ float to_tf32(float x) {
    float r;
    asm("cvt.rna.tf32.f32 %0, %1;" : "=f"(r) : "f"(x));
    return r;
}

__device__ __forceinline__ uint32_t smem_u32(const void* p) {
    uint32_t a;
    asm("{ .reg .u64 t; cvta.to.shared.u64 t, %1; cvt.u32.u64 %0, t; }"
        : "=r"(a) : "l"(p));
    return a;
}

#define CP_ASYNC16(dst, src) \
    asm volatile("cp.async.cg.shared.global [%0], [%1], 16;" :: "r"(dst), "l"(src))
#define CP_COMMIT()  asm volatile("cp.async.commit_group;" ::: "memory")
#define CP_WAIT(n)   asm volatile("cp.async.wait_group %0;" :: "n"(n) : "memory")

// m16n8k8 tf32 mma (sm_80+ PTX, lowers to HMMA on sm_103)
#define MMA_TF32(d, a, b) \
    asm volatile("mma.sync.aligned.m16n8k8.row.col.f32.tf32.tf32.f32 " \
        "{%0,%1,%2,%3}, {%4,%5,%6,%7}, {%8,%9}, {%0,%1,%2,%3};" \
        : "+f"(d[0]), "+f"(d[1]), "+f"(d[2]), "+f"(d[3]) \
        : "r"(a[0]), "r"(a[1]), "r"(a[2]), "r"(a[3]), "r"(b[0]), "r"(b[1]))

// ---------------------------------------------------------------------------
// LayerNorm (+ tf32 rounding; output always feeds a GEMM A operand)
// ---------------------------------------------------------------------------
__global__ __launch_bounds__(256) void ln_kernel(
    const float* __restrict__ X, const float* __restrict__ gamma,
    const float* __restrict__ beta, float* __restrict__ out)
{
    const int row = blockIdx.x;
    const int t   = threadIdx.x;
    const float4 v = ((const float4*)(X + (size_t)row*DM))[t];

    float s  = v.x + v.y + v.z + v.w;
    float ss = v.x*v.x + v.y*v.y + v.z*v.z + v.w*v.w;

    #pragma unroll
    for (int o = 16; o > 0; o >>= 1) {
        s  += __shfl_xor_sync(0xffffffffu, s,  o);
        ss += __shfl_xor_sync(0xffffffffu, ss, o);
    }
    __shared__ float sh_s[8], sh_ss[8];
    const int w = t >> 5, lane = t & 31;
    if (lane == 0) { sh_s[w] = s; sh_ss[w] = ss; }
    __syncthreads();
    if (w == 0) {
        s  = (lane < 8) ? sh_s[lane]  : 0.f;
        ss = (lane < 8) ? sh_ss[lane] : 0.f;
        #pragma unroll
        for (int o = 4; o > 0; o >>= 1) {
            s  += __shfl_xor_sync(0xffffffffu, s,  o);
            ss += __shfl_xor_sync(0xffffffffu, ss, o);
        }
        if (lane == 0) { sh_s[0] = s; sh_ss[0] = ss; }
    }
    __syncthreads();
    s = sh_s[0]; ss = sh_ss[0];

    const float mu   = s * (1.0f / DM);
    const float var  = ss * (1.0f / DM) - mu*mu;
    const float rstd = rsqrtf(var + LN_EPS);

    const float4 g4 = ((const float4*)gamma)[t];
    const float4 b4 = ((const float4*)beta)[t];
    float4 o4;
    o4.x = to_tf32((v.x - mu)*rstd*g4.x + b4.x);
    o4.y = to_tf32((v.y - mu)*rstd*g4.y + b4.y);
    o4.z = to_tf32((v.z - mu)*rstd*g4.z + b4.z);
    o4.w = to_tf32((v.w - mu)*rstd*g4.w + b4.w);
    ((float4*)(out + (size_t)row*DM))[t] = o4;
}

// ---------------------------------------------------------------------------
// Weight transpose + tf32 rounding: W[K,N] -> Wt[N,K]
// ---------------------------------------------------------------------------
__global__ __launch_bounds__(256) void transpose_round(
    const float* __restrict__ W, float* __restrict__ Wt, int K, int N)
{
    __shared__ float tile[32][33];
    const int tx = threadIdx.x, ty = threadIdx.y;
    const int n0 = blockIdx.x * 32, k0 = blockIdx.y * 32;
    #pragma unroll
    for (int i = ty; i < 32; i += 8)
        tile[i][tx] = W[(size_t)(k0 + i)*N + n0 + tx];
    __syncthreads();
    #pragma unroll
    for (int i = ty; i < 32; i += 8)
        Wt[(size_t)(n0 + i)*K + k0 + tx] = to_tf32(tile[tx][i]);
}

// ---------------------------------------------------------------------------
// tf32 mma.sync GEMM: C[M,N] = A[M,K] @ Bt[N,K]^T + bias (+relu)(+res)(+round)
// 128x128 CTA tile, BK=32, 3-stage cp.async pipeline, 256 threads (8 warps).
// Warp grid 2(m) x 4(n): each warp 64x32, 4x4 m16n8k8 tiles, 64 acc regs.
// SMEM: A/B tiles stored [128][36] (pad 4 -> conflict-free fragment loads).
// ---------------------------------------------------------------------------
#define GST   3
#define LDT   36
#define TSZ   (128*LDT)                 // floats per tile
#define STAGE_FLOATS (2*TSZ)            // A + B
#define GEMM_SMEM (GST*STAGE_FLOATS*4)  // 110592 bytes

template<bool RELU, bool RES, bool ROUND>
__global__ __launch_bounds__(256, 1) void mma_gemm(
    const float* __restrict__ A, const float* __restrict__ Bt,
    const float* __restrict__ bias, const float* __restrict__ res,
    float* __restrict__ C, int M, int N, int K)
{
    extern __shared__ float sm[];
    const uint32_t sm_b = smem_u32(sm);

    const int tid  = threadIdx.x;
    const int lane = tid & 31, wid = tid >> 5;
    const int wm = wid >> 2, wn = wid & 3;        // 2 x 4 warp grid
    const int gid = lane >> 2, tg = lane & 3;
    const int bx = blockIdx.x, by = blockIdx.y;

    const float* Ab = A  + (size_t)by * 128 * K;
    const float* Bb = Bt + (size_t)bx * 128 * K;
    const int nchunks = K >> 5;

    // Async tile loader: 128 rows x 32 floats, rows padded to 36 floats.
    const int l_r = tid >> 3;            // 0..31 base row (4 iters of +32)
    const int l_c = tid & 7;             // 16B column index 0..7
    auto load_stage = [&](int st, int kt) {
        const uint32_t a_dst = sm_b + (uint32_t)(st*STAGE_FLOATS)*4;
        const uint32_t b_dst = a_dst + TSZ*4;
        const float* as = Ab + (size_t)kt*32;
        const float* bs = Bb + (size_t)kt*32;
        #pragma unroll
        for (int it = 0; it < 4; it++) {
            const int r = l_r + it*32;
            const uint32_t off = (uint32_t)(r*LDT + l_c*4) * 4;
            CP_ASYNC16(a_dst + off, as + (size_t)r*K + l_c*4);
            CP_ASYNC16(b_dst + off, bs + (size_t)r*K + l_c*4);
        }
        CP_COMMIT();
    };

    float acc[4][4][4];
    #pragma unroll
    for (int i = 0; i < 4; i++)
        #pragma unroll
        for (int j = 0; j < 4; j++)
            #pragma unroll
            for (int k = 0; k < 4; k++) acc[i][j][k] = 0.f;

    // Prologue: fill GST-1 stages
    load_stage(0, 0);
    load_stage(1, 1);

    for (int i = 0; i < nchunks; i++) {
        const int st = i % GST;
        if (i + 1 < nchunks) { CP_WAIT(1); } else { CP_WAIT(0); }
        __syncthreads();

        if (i + (GST-1) < nchunks)
            load_stage((i + GST - 1) % GST, i + GST - 1);

        const uint32_t* as = (const uint32_t*)(sm + st*STAGE_FLOATS);
        const uint32_t* bs = as + TSZ;

        #pragma unroll
        for (int kk = 0; kk < 4; kk++) {
            const int k0 = kk*8;
            uint32_t a[4][4], b[4][2];
            #pragma unroll
            for (int mt = 0; mt < 4; mt++) {
                const int m0 = wm*64 + mt*16 + gid;
                a[mt][0] = as[m0*LDT + k0 + tg];
                a[mt][1] = as[(m0+8)*LDT + k0 + tg];
                a[mt][2] = as[m0*LDT + k0 + tg + 4];
                a[mt][3] = as[(m0+8)*LDT + k0 + tg + 4];
            }
            #pragma unroll
            for (int nt = 0; nt < 4; nt++) {
                const int n0 = wn*32 + nt*8 + gid;
                b[nt][0] = bs[n0*LDT + k0 + tg];
                b[nt][1] = bs[n0*LDT + k0 + tg + 4];
            }
            #pragma unroll
            for (int mt = 0; mt < 4; mt++)
                #pragma unroll
                for (int nt = 0; nt < 4; nt++)
                    MMA_TF32(acc[mt][nt], a[mt], b[nt]);
        }
        __syncthreads();
    }

    // Epilogue: c0,c1 -> (row, 2tg..2tg+1), c2,c3 -> (row+8, ...)
    #pragma unroll
    for (int mt = 0; mt < 4; mt++) {
        #pragma unroll
        for (int nt = 0; nt < 4; nt++) {
            const int r0 = by*128 + wm*64 + mt*16 + gid;
            const int c  = bx*128 + wn*32 + nt*8 + tg*2;
            const float2 b2 = *(const float2*)(bias + c);
            #pragma unroll
            for (int half = 0; half < 2; half++) {
                const int r = r0 + half*8;
                float2 o;
                o.x = acc[mt][nt][half*2+0] + b2.x;
                o.y = acc[mt][nt][half*2+1] + b2.y;
                if (RELU) { o.x = fmaxf(o.x, 0.f); o.y = fmaxf(o.y, 0.f); }
                if (RES) {
                    const float2 r2 = *(const float2*)(res + (size_t)r*N + c);
                    o.x += r2.x; o.y += r2.y;
                }
                if (ROUND) { o.x = to_tf32(o.x); o.y = to_tf32(o.y); }
                *(float2*)(C + (size_t)r*N + c) = o;
            }
        }
    }
}

// ---------------------------------------------------------------------------
// Causal flash attention, fp32, d_k=64. tf32-rounded output (feeds Wo GEMM).
// ---------------------------------------------------------------------------
__global__ __launch_bounds__(64) void attn_kernel(
    const float* __restrict__ Q, const float* __restrict__ K,
    const float* __restrict__ V, float* __restrict__ O)
{
    const int qt = blockIdx.x;
    const int bh = blockIdx.y;
    const int b  = bh >> 4;
    const int h  = bh & 15;
    const int t  = threadIdx.x;
    const int qg = qt*64 + t;

    __shared__ float Ks[64][64];
    __shared__ float Vs[64][64];

    const float* qp = Q + ((size_t)(b*SS + qg))*DM + h*DK;
    float q[DK];
    #pragma unroll
    for (int k = 0; k < DK; k += 4) {
        const float4 v4 = *(const float4*)(qp + k);
        q[k] = v4.x; q[k+1] = v4.y; q[k+2] = v4.z; q[k+3] = v4.w;
    }

    float acc[DK];
    #pragma unroll
    for (int d = 0; d < DK; d++) acc[d] = 0.f;
    float m = -INFINITY, l = 0.f;
    const float scale = 0.125f;

    for (int kt = 0; kt <= qt; kt++) {
        __syncthreads();
        const float* kb = K + ((size_t)(b*SS + kt*64))*DM + h*DK;
        const float* vb = V + ((size_t)(b*SS + kt*64))*DM + h*DK;
        #pragma unroll
        for (int i = 0; i < 16; i++) {
            const int idx = i*64 + t;
            const int r = idx >> 4;
            const int c = (idx & 15) << 2;
            *(float4*)&Ks[r][c] = *(const float4*)(kb + (size_t)r*DM + c);
            *(float4*)&Vs[r][c] = *(const float4*)(vb + (size_t)r*DM + c);
        }
        __syncthreads();

        const int jmax = (kt == qt) ? (t + 1) : 64;
        for (int j = 0; j < jmax; j++) {
            float s = 0.f;
            #pragma unroll
            for (int k = 0; k < DK; k += 4) {
                const float4 kv = *(const float4*)&Ks[j][k];
                s += q[k]*kv.x + q[k+1]*kv.y + q[k+2]*kv.z + q[k+3]*kv.w;
            }
            s *= scale;

            const float mn = fmaxf(m, s);
            if (mn > m) {
                const float corr = __expf(m - mn);
                l *= corr;
                #pragma unroll
                for (int d = 0; d < DK; d++) acc[d] *= corr;
                m = mn;
            }
            const float p = __expf(s - m);
            l += p;
            #pragma unroll
            for (int d = 0; d < DK; d += 4) {
                const float4 vv = *(const float4*)&Vs[j][d];
                acc[d]   += p*vv.x; acc[d+1] += p*vv.y;
                acc[d+2] += p*vv.z; acc[d+3] += p*vv.w;
            }
        }
    }

    const float inv = 1.0f / l;
    float* op = O + ((size_t)(b*SS + qg))*DM + h*DK;
    #pragma unroll
    for (int d = 0; d < DK; d += 4) {
        float4 o4;
        o4.x = to_tf32(acc[d]*inv);   o4.y = to_tf32(acc[d+1]*inv);
        o4.z = to_tf32(acc[d+2]*inv); o4.w = to_tf32(acc[d+3]*inv);
        *(float4*)(op + d) = o4;
    }
}

// ---------------------------------------------------------------------------
// Launch
// ---------------------------------------------------------------------------
extern "C" void kernel_launch(void* const* d_in, const int* in_sizes, int n_in,
                              void* d_out, int out_size)
{
    const float* x   = (const float*)d_in[0];
    const float* Wq  = (const float*)d_in[1];
    const float* bq  = (const float*)d_in[2];
    const float* Wk  = (const float*)d_in[3];
    const float* bk  = (const float*)d_in[4];
    const float* Wv  = (const float*)d_in[5];
    const float* bv  = (const float*)d_in[6];
    const float* Wo  = (const float*)d_in[7];
    const float* bo  = (const float*)d_in[8];
    const float* W1  = (const float*)d_in[9];
    const float* b1  = (const float*)d_in[10];
    const float* W2  = (const float*)d_in[11];
    const float* b2  = (const float*)d_in[12];
    const float* g1  = (const float*)d_in[13];
    const float* be1 = (const float*)d_in[14];
    const float* g2  = (const float*)d_in[15];
    const float* be2 = (const float*)d_in[16];
    float* out = (float*)d_out;

    float *p_h, *p_q, *p_k, *p_v, *p_o, *p_x1, *p_ff;
    float *p_wqt, *p_wkt, *p_wvt, *p_wot, *p_w1t, *p_w2t;
    cudaGetSymbolAddress((void**)&p_h,   g_h);
    cudaGetSymbolAddress((void**)&p_q,   g_q);
    cudaGetSymbolAddress((void**)&p_k,   g_k);
    cudaGetSymbolAddress((void**)&p_v,   g_v);
    cudaGetSymbolAddress((void**)&p_o,   g_o);
    cudaGetSymbolAddress((void**)&p_x1,  g_x1);
    cudaGetSymbolAddress((void**)&p_ff,  g_ff);
    cudaGetSymbolAddress((void**)&p_wqt, g_wqt);
    cudaGetSymbolAddress((void**)&p_wkt, g_wkt);
    cudaGetSymbolAddress((void**)&p_wvt, g_wvt);
    cudaGetSymbolAddress((void**)&p_wot, g_wot);
    cudaGetSymbolAddress((void**)&p_w1t, g_w1t);
    cudaGetSymbolAddress((void**)&p_w2t, g_w2t);

    static bool attr_set = false;
    if (!attr_set) {
        cudaFuncSetAttribute(mma_gemm<false,false,false>,
                             cudaFuncAttributeMaxDynamicSharedMemorySize, GEMM_SMEM);
        cudaFuncSetAttribute(mma_gemm<false,true,false>,
                             cudaFuncAttributeMaxDynamicSharedMemorySize, GEMM_SMEM);
        cudaFuncSetAttribute(mma_gemm<true,false,true>,
                             cudaFuncAttributeMaxDynamicSharedMemorySize, GEMM_SMEM);
        attr_set = true;
    }

    const dim3 tblk(32, 8);
    // Weight prep: transpose + tf32 rounding
    transpose_round<<<dim3(DM/32,  DM/32),  tblk>>>(Wq, p_wqt, DM,  DM);
    transpose_round<<<dim3(DM/32,  DM/32),  tblk>>>(Wk, p_wkt, DM,  DM);
    transpose_round<<<dim3(DM/32,  DM/32),  tblk>>>(Wv, p_wvt, DM,  DM);
    transpose_round<<<dim3(DM/32,  DM/32),  tblk>>>(Wo, p_wot, DM,  DM);
    transpose_round<<<dim3(DFF/32, DM/32),  tblk>>>(W1, p_w1t, DM,  DFF);
    transpose_round<<<dim3(DM/32,  DFF/32), tblk>>>(W2, p_w2t, DFF, DM);

    const dim3 gD (DM/128,  MROWS/128);   // (8, 64)
    const dim3 gF (DFF/128, MROWS/128);   // (32, 64)

    // 1. ln1(x) -> h (tf32-rounded)
    ln_kernel<<<MROWS, 256>>>(x, g1, be1, p_h);
    // 2-4. Q/K/V projections (tensor pipe, tf32 mma.sync)
    mma_gemm<false,false,false><<<gD, 256, GEMM_SMEM>>>(p_h, p_wqt, bq, nullptr, p_q, MROWS, DM, DM);
    mma_gemm<false,false,false><<<gD, 256, GEMM_SMEM>>>(p_h, p_wkt, bk, nullptr, p_k, MROWS, DM, DM);
    mma_gemm<false,false,false><<<gD, 256, GEMM_SMEM>>>(p_h, p_wvt, bv, nullptr, p_v, MROWS, DM, DM);
    // 5. causal attention (fp32)
    attn_kernel<<<dim3(SS/64, BB*HH), 64>>>(p_q, p_k, p_v, p_o);
    // 6. output projection + residual(x) -> x1
    mma_gemm<false,true,false><<<gD, 256, GEMM_SMEM>>>(p_o, p_wot, bo, x, p_x1, MROWS, DM, DM);
    // 7. ln2(x1) -> h (tf32-rounded)
    ln_kernel<<<MROWS, 256>>>(p_x1, g2, be2, p_h);
    // 8. FFN up + ReLU (tf32-rounded output)
    mma_gemm<true,false,true><<<gF, 256, GEMM_SMEM>>>(p_h, p_w1t, b1, nullptr, p_ff, MROWS, DFF, DM);
    // 9. FFN down + residual(x1) -> out
    mma_gemm<false,true,false><<<gD, 256, GEMM_SMEM>>>(p_ff, p_w2t, b2, p_x1, out, MROWS, DM, DFF);
}

// round 4
// speedup vs baseline: 5.0823x; 1.6139x over previous
#include <cuda_runtime.h>
#include <cuda_bf16.h>
#include <math.h>
#include <stdint.h>

// Problem dimensions (fixed by the reference)
#define BB    4
#define SS    2048
#define DM    1024
#define HH    16
#define DK    64
#define DFF   4096
#define MROWS (BB*SS)          // 8192
#define LN_EPS 1e-5f

// ---------------------------------------------------------------------------
// Scratch (device globals; no allocations allowed)
// ---------------------------------------------------------------------------
__device__ float g_h  [MROWS*DM];    // ln1 / ln2 output (tf32-rounded)
__device__ float g_q  [MROWS*DM];
__device__ float g_k  [MROWS*DM];
__device__ float g_v  [MROWS*DM];
__device__ float g_o  [MROWS*DM];    // attention output (tf32-rounded)
__device__ float g_x1 [MROWS*DM];    // residual after attention
__device__ float g_ff [MROWS*DFF];   // FFN hidden (tf32-rounded)
__device__ float g_wqt[DM*DM];       // transposed + tf32-rounded weights [N,K]
__device__ float g_wkt[DM*DM];
__device__ float g_wvt[DM*DM];
__device__ float g_wot[DM*DM];
__device__ float g_w1t[DFF*DM];      // [4096,1024]
__device__ float g_w2t[DM*DFF];      // [1024,4096]

// ---------------------------------------------------------------------------
// Helpers
// ---------------------------------------------------------------------------
__device__ __forceinline__ float to_tf32(float x) {
    float r;
    asm("cvt.rna.tf32.f32 %0, %1;" : "=f"(r) : "f"(x));
    return r;
}

__device__ __forceinline__ uint32_t smem_u32(const void* p) {
    uint32_t a;
    asm("{ .reg .u64 t; cvta.to.shared.u64 t, %1; cvt.u32.u64 %0, t; }"
        : "=r"(a) : "l"(p));
    return a;
}

#define CP_ASYNC16(dst, src) \
    asm volatile("cp.async.cg.shared.global [%0], [%1], 16;" :: "r"(dst), "l"(src))
#define CP_COMMIT()  asm volatile("cp.async.commit_group;" ::: "memory")
#define CP_WAIT(n)   asm volatile("cp.async.wait_group %0;" :: "n"(n) : "memory")

// m16n8k8 tf32 mma (sm_80+ PTX, lowers to HMMA on sm_103)
#define MMA_TF32(d, a, b) \
    asm volatile("mma.sync.aligned.m16n8k8.row.col.f32.tf32.tf32.f32 " \
        "{%0,%1,%2,%3}, {%4,%5,%6,%7}, {%8,%9}, {%0,%1,%2,%3};" \
        : "+f"(d[0]), "+f"(d[1]), "+f"(d[2]), "+f"(d[3]) \
        : "r"(a[0]), "r"(a[1]), "r"(a[2]), "r"(a[3]), "r"(b[0]), "r"(b[1]))

#define MMA_TF32_S(d, a, b0, b1) \
    asm volatile("mma.sync.aligned.m16n8k8.row.col.f32.tf32.tf32.f32 " \
        "{%0,%1,%2,%3}, {%4,%5,%6,%7}, {%8,%9}, {%0,%1,%2,%3};" \
        : "+f"(d[0]), "+f"(d[1]), "+f"(d[2]), "+f"(d[3]) \
        : "r"(a[0]), "r"(a[1]), "r"(a[2]), "r"(a[3]), "r"(b0), "r"(b1))

// ---------------------------------------------------------------------------
// LayerNorm (+ tf32 rounding; output always feeds a GEMM A operand)
// ---------------------------------------------------------------------------
__global__ __launch_bounds__(256) void ln_kernel(
    const float* __restrict__ X, const float* __restrict__ gamma,
    const float* __restrict__ beta, float* __restrict__ out)
{
    const int row = blockIdx.x;
    const int t   = threadIdx.x;
    const float4 v = ((const float4*)(X + (size_t)row*DM))[t];

    float s  = v.x + v.y + v.z + v.w;
    float ss = v.x*v.x + v.y*v.y + v.z*v.z + v.w*v.w;

    #pragma unroll
    for (int o = 16; o > 0; o >>= 1) {
        s  += __shfl_xor_sync(0xffffffffu, s,  o);
        ss += __shfl_xor_sync(0xffffffffu, ss, o);
    }
    __shared__ float sh_s[8], sh_ss[8];
    const int w = t >> 5, lane = t & 31;
    if (lane == 0) { sh_s[w] = s; sh_ss[w] = ss; }
    __syncthreads();
    if (w == 0) {
        s  = (lane < 8) ? sh_s[lane]  : 0.f;
        ss = (lane < 8) ? sh_ss[lane] : 0.f;
        #pragma unroll
        for (int o = 4; o > 0; o >>= 1) {
            s  += __shfl_xor_sync(0xffffffffu, s,  o);
            ss += __shfl_xor_sync(0xffffffffu, ss, o);
        }
        if (lane == 0) { sh_s[0] = s; sh_ss[0] = ss; }
    }
    __syncthreads();
    s = sh_s[0]; ss = sh_ss[0];

    const float mu   = s * (1.0f / DM);
    const float var  = ss * (1.0f / DM) - mu*mu;
    const float rstd = rsqrtf(var + LN_EPS);

    const float4 g4 = ((const float4*)gamma)[t];
    const float4 b4 = ((const float4*)beta)[t];
    float4 o4;
    o4.x = to_tf32((v.x - mu)*rstd*g4.x + b4.x);
    o4.y = to_tf32((v.y - mu)*rstd*g4.y + b4.y);
    o4.z = to_tf32((v.z - mu)*rstd*g4.z + b4.z);
    o4.w = to_tf32((v.w - mu)*rstd*g4.w + b4.w);
    ((float4*)(out + (size_t)row*DM))[t] = o4;
}

// ---------------------------------------------------------------------------
// Weight transpose + tf32 rounding: W[K,N] -> Wt[N,K]
// ---------------------------------------------------------------------------
__global__ __launch_bounds__(256) void transpose_round(
    const float* __restrict__ W, float* __restrict__ Wt, int K, int N)
{
    __shared__ float tile[32][33];
    const int tx = threadIdx.x, ty = threadIdx.y;
    const int n0 = blockIdx.x * 32, k0 = blockIdx.y * 32;
    #pragma unroll
    for (int i = ty; i < 32; i += 8)
        tile[i][tx] = W[(size_t)(k0 + i)*N + n0 + tx];
    __syncthreads();
    #pragma unroll
    for (int i = ty; i < 32; i += 8)
        Wt[(size_t)(n0 + i)*K + k0 + tx] = to_tf32(tile[tx][i]);
}

// ---------------------------------------------------------------------------
// tf32 mma.sync GEMM: C[M,N] = A[M,K] @ Bt[N,K]^T + bias (+relu)(+res)(+round)
// 128x128 CTA tile, BK=32, 3-stage cp.async pipeline, 256 threads (8 warps).
// ---------------------------------------------------------------------------
#define GST   3
#define LDT   36
#define TSZ   (128*LDT)                 // floats per tile
#define STAGE_FLOATS (2*TSZ)            // A + B
#define GEMM_SMEM (GST*STAGE_FLOATS*4)  // 110592 bytes

template<bool RELU, bool RES, bool ROUND>
__global__ __launch_bounds__(256, 1) void mma_gemm(
    const float* __restrict__ A, const float* __restrict__ Bt,
    const float* __restrict__ bias, const float* __restrict__ res,
    float* __restrict__ C, int M, int N, int K)
{
    extern __shared__ float sm[];
    const uint32_t sm_b = smem_u32(sm);

    const int tid  = threadIdx.x;
    const int lane = tid & 31, wid = tid >> 5;
    const int wm = wid >> 2, wn = wid & 3;        // 2 x 4 warp grid
    const int gid = lane >> 2, tg = lane & 3;
    const int bx = blockIdx.x, by = blockIdx.y;

    const float* Ab = A  + (size_t)by * 128 * K;
    const float* Bb = Bt + (size_t)bx * 128 * K;
    const int nchunks = K >> 5;

    const int l_r = tid >> 3;
    const int l_c = tid & 7;
    auto load_stage = [&](int st, int kt) {
        const uint32_t a_dst = sm_b + (uint32_t)(st*STAGE_FLOATS)*4;
        const uint32_t b_dst = a_dst + TSZ*4;
        const float* as = Ab + (size_t)kt*32;
        const float* bs = Bb + (size_t)kt*32;
        #pragma unroll
        for (int it = 0; it < 4; it++) {
            const int r = l_r + it*32;
            const uint32_t off = (uint32_t)(r*LDT + l_c*4) * 4;
            CP_ASYNC16(a_dst + off, as + (size_t)r*K + l_c*4);
            CP_ASYNC16(b_dst + off, bs + (size_t)r*K + l_c*4);
        }
        CP_COMMIT();
    };

    float acc[4][4][4];
    #pragma unroll
    for (int i = 0; i < 4; i++)
        #pragma unroll
        for (int j = 0; j < 4; j++)
            #pragma unroll
            for (int k = 0; k < 4; k++) acc[i][j][k] = 0.f;

    load_stage(0, 0);
    load_stage(1, 1);

    for (int i = 0; i < nchunks; i++) {
        const int st = i % GST;
        if (i + 1 < nchunks) { CP_WAIT(1); } else { CP_WAIT(0); }
        __syncthreads();

        if (i + (GST-1) < nchunks)
            load_stage((i + GST - 1) % GST, i + GST - 1);

        const uint32_t* as = (const uint32_t*)(sm + st*STAGE_FLOATS);
        const uint32_t* bs = as + TSZ;

        #pragma unroll
        for (int kk = 0; kk < 4; kk++) {
            const int k0 = kk*8;
            uint32_t a[4][4], b[4][2];
            #pragma unroll
            for (int mt = 0; mt < 4; mt++) {
                const int m0 = wm*64 + mt*16 + gid;
                a[mt][0] = as[m0*LDT + k0 + tg];
                a[mt][1] = as[(m0+8)*LDT + k0 + tg];
                a[mt][2] = as[m0*LDT + k0 + tg + 4];
                a[mt][3] = as[(m0+8)*LDT + k0 + tg + 4];
            }
            #pragma unroll
            for (int nt = 0; nt < 4; nt++) {
                const int n0 = wn*32 + nt*8 + gid;
                b[nt][0] = bs[n0*LDT + k0 + tg];
                b[nt][1] = bs[n0*LDT + k0 + tg + 4];
            }
            #pragma unroll
            for (int mt = 0; mt < 4; mt++)
                #pragma unroll
                for (int nt = 0; nt < 4; nt++)
                    MMA_TF32(acc[mt][nt], a[mt], b[nt]);
        }
        __syncthreads();
    }

    #pragma unroll
    for (int mt = 0; mt < 4; mt++) {
        #pragma unroll
        for (int nt = 0; nt < 4; nt++) {
            const int r0 = by*128 + wm*64 + mt*16 + gid;
            const int c  = bx*128 + wn*32 + nt*8 + tg*2;
            const float2 b2 = *(const float2*)(bias + c);
            #pragma unroll
            for (int half = 0; half < 2; half++) {
                const int r = r0 + half*8;
                float2 o;
                o.x = acc[mt][nt][half*2+0] + b2.x;
                o.y = acc[mt][nt][half*2+1] + b2.y;
                if (RELU) { o.x = fmaxf(o.x, 0.f); o.y = fmaxf(o.y, 0.f); }
                if (RES) {
                    const float2 r2 = *(const float2*)(res + (size_t)r*N + c);
                    o.x += r2.x; o.y += r2.y;
                }
                if (ROUND) { o.x = to_tf32(o.x); o.y = to_tf32(o.y); }
                *(float2*)(C + (size_t)r*N + c) = o;
            }
        }
    }
}

// ---------------------------------------------------------------------------
// Tensor-core causal flash attention, tf32 mma.sync, d_k=64.
// CTA: 128 threads (4 warps), 64 q rows (16 per warp), 64-key KV tiles,
// double-buffered cp.async. P accumulator reused directly as PV A-operand
// via k-slot permutation (slot tg <-> s=2tg, slot tg+4 <-> s=2tg+1).
// Q/K/V are tf32-pre-rounded by the producing GEMMs.
// ---------------------------------------------------------------------------
#define ALD 68
#define ATT_TILE (64*ALD)                 // floats per 64x64 tile (padded)
#define ATT_SMEM (4*ATT_TILE*4)           // 2 stages x (K+V) = 69632 bytes

__global__ __launch_bounds__(128) void fa_kernel(
    const float* __restrict__ Q, const float* __restrict__ K,
    const float* __restrict__ V, float* __restrict__ O)
{
    extern __shared__ float fsm[];
    const int tid  = threadIdx.x;
    const int lane = tid & 31, w = tid >> 5;
    const int gid  = lane >> 2, tg = lane & 3;
    const int qt   = (int)gridDim.x - 1 - (int)blockIdx.x;   // big tiles first
    const int bh   = blockIdx.y;
    const int b    = bh >> 4, h = bh & 15;
    const int qbase = qt * 64;

    float* Ks[2] = { fsm,              fsm + 2*ATT_TILE };
    float* Vs[2] = { fsm + ATT_TILE,   fsm + 3*ATT_TILE };

    const int l_r = tid >> 4;           // 0..7
    const int l_c = tid & 15;           // 0..15 (16B units)
    auto load_tile_nc = [&](float* dst, const float* src) {
        const uint32_t d0 = smem_u32(dst);
        #pragma unroll
        for (int i = 0; i < 8; i++) {
            const int r = i*8 + l_r;
            CP_ASYNC16(d0 + (uint32_t)(r*ALD + l_c*4)*4, src + (size_t)r*DM + l_c*4);
        }
    };

    const float* Kg = K + ((size_t)(b*SS))*DM + h*DK;
    const float* Vg = V + ((size_t)(b*SS))*DM + h*DK;
    auto load_kv = [&](int st, int kt) {
        load_tile_nc(Ks[st], Kg + (size_t)(kt*64)*DM);
        load_tile_nc(Vs[st], Vg + (size_t)(kt*64)*DM);
        CP_COMMIT();
    };

    // --- Stage Q through smem, build scaled tf32 fragments in registers ---
    load_tile_nc(Ks[0], Q + ((size_t)(b*SS + qbase))*DM + h*DK);
    CP_COMMIT();
    CP_WAIT(0);
    __syncthreads();

    uint32_t qf[8][4];
    {
        const float* qs = Ks[0];
        const int m0 = w*16 + gid;
        #pragma unroll
        for (int k0 = 0; k0 < 8; k0++) {
            // Q already tf32; x0.125 is exact (power of 2) -> still tf32
            qf[k0][0] = __float_as_uint(0.125f * qs[m0*ALD + k0*8 + tg]);
            qf[k0][1] = __float_as_uint(0.125f * qs[(m0+8)*ALD + k0*8 + tg]);
            qf[k0][2] = __float_as_uint(0.125f * qs[m0*ALD + k0*8 + tg + 4]);
            qf[k0][3] = __float_as_uint(0.125f * qs[(m0+8)*ALD + k0*8 + tg + 4]);
        }
    }
    __syncthreads();

    // --- Pipeline prologue ---
    load_kv(0, 0);
    if (qt >= 1) load_kv(1, 1);

    float oacc[8][4];
    #pragma unroll
    for (int d = 0; d < 8; d++) {
        oacc[d][0] = 0.f; oacc[d][1] = 0.f; oacc[d][2] = 0.f; oacc[d][3] = 0.f;
    }
    float m0r = -INFINITY, m1r = -INFINITY, l0 = 0.f, l1 = 0.f;

    for (int kt = 0; kt <= qt; kt++) {
        const int st = kt & 1;
        if (kt < qt) { CP_WAIT(1); } else { CP_WAIT(0); }
        __syncthreads();
        const float* ks = Ks[st];
        const float* vs = Vs[st];

        // ---- S = Q K^T (scaled) ----
        float sacc[8][4];
        #pragma unroll
        for (int nt = 0; nt < 8; nt++) {
            sacc[nt][0] = 0.f; sacc[nt][1] = 0.f; sacc[nt][2] = 0.f; sacc[nt][3] = 0.f;
        }
        #pragma unroll
        for (int k0 = 0; k0 < 8; k0++) {
            #pragma unroll
            for (int nt = 0; nt < 8; nt++) {
                const uint32_t b0 = __float_as_uint(ks[(nt*8+gid)*ALD + k0*8 + tg]);
                const uint32_t b1 = __float_as_uint(ks[(nt*8+gid)*ALD + k0*8 + tg + 4]);
                MMA_TF32_S(sacc[nt], qf[k0], b0, b1);
            }
        }

        // ---- causal mask (diagonal tile only) ----
        if (kt == qt) {
            const int q0 = w*16 + gid;
            #pragma unroll
            for (int nt = 0; nt < 8; nt++) {
                const int s0 = nt*8 + 2*tg;
                if (s0     > q0)     sacc[nt][0] = -1e30f;
                if (s0 + 1 > q0)     sacc[nt][1] = -1e30f;
                if (s0     > q0 + 8) sacc[nt][2] = -1e30f;
                if (s0 + 1 > q0 + 8) sacc[nt][3] = -1e30f;
            }
        }

        // ---- online softmax ----
        float t0 = -1e30f, t1 = -1e30f;
        #pragma unroll
        for (int nt = 0; nt < 8; nt++) {
            t0 = fmaxf(t0, fmaxf(sacc[nt][0], sacc[nt][1]));
            t1 = fmaxf(t1, fmaxf(sacc[nt][2], sacc[nt][3]));
        }
        t0 = fmaxf(t0, __shfl_xor_sync(0xffffffffu, t0, 1));
        t0 = fmaxf(t0, __shfl_xor_sync(0xffffffffu, t0, 2));
        t1 = fmaxf(t1, __shfl_xor_sync(0xffffffffu, t1, 1));
        t1 = fmaxf(t1, __shfl_xor_sync(0xffffffffu, t1, 2));

        const float mn0 = fmaxf(m0r, t0), mn1 = fmaxf(m1r, t1);
        const float cr0 = __expf(m0r - mn0), cr1 = __expf(m1r - mn1);
        m0r = mn0; m1r = mn1;
        l0 *= cr0; l1 *= cr1;
        #pragma unroll
        for (int d = 0; d < 8; d++) {
            oacc[d][0] *= cr0; oacc[d][1] *= cr0;
            oacc[d][2] *= cr1; oacc[d][3] *= cr1;
        }

        float s0 = 0.f, s1 = 0.f;
        #pragma unroll
        for (int nt = 0; nt < 8; nt++) {
            float p0 = to_tf32(__expf(sacc[nt][0] - mn0));
            float p1 = to_tf32(__expf(sacc[nt][1] - mn0));
            float p2 = to_tf32(__expf(sacc[nt][2] - mn1));
            float p3 = to_tf32(__expf(sacc[nt][3] - mn1));
            s0 += p0 + p1; s1 += p2 + p3;
            sacc[nt][0] = p0; sacc[nt][1] = p1; sacc[nt][2] = p2; sacc[nt][3] = p3;
        }
        s0 += __shfl_xor_sync(0xffffffffu, s0, 1);
        s0 += __shfl_xor_sync(0xffffffffu, s0, 2);
        s1 += __shfl_xor_sync(0xffffffffu, s1, 1);
        s1 += __shfl_xor_sync(0xffffffffu, s1, 2);
        l0 += s0; l1 += s1;

        // ---- O += P V (P acc reused as A with permuted k-slots) ----
        #pragma unroll
        for (int nt = 0; nt < 8; nt++) {
            uint32_t a[4];
            a[0] = __float_as_uint(sacc[nt][0]);   // (gid,   s=2tg)   slot tg
            a[1] = __float_as_uint(sacc[nt][2]);   // (gid+8, s=2tg)
            a[2] = __float_as_uint(sacc[nt][1]);   // (gid,   s=2tg+1) slot tg+4
            a[3] = __float_as_uint(sacc[nt][3]);   // (gid+8, s=2tg+1)
            #pragma unroll
            for (int dt = 0; dt < 8; dt++) {
                const uint32_t b0 = __float_as_uint(vs[(nt*8 + 2*tg)*ALD + dt*8 + gid]);
                const uint32_t b1 = __float_as_uint(vs[(nt*8 + 2*tg + 1)*ALD + dt*8 + gid]);
                MMA_TF32_S(oacc[dt], a, b0, b1);
            }
        }
        __syncthreads();

        if (kt + 2 <= qt) load_kv(st, kt + 2);
    }

    // ---- normalize + write (tf32-rounded; feeds Wo GEMM) ----
    const float inv0 = 1.0f / l0, inv1 = 1.0f / l1;
    const int r0 = b*SS + qbase + w*16 + gid;
    float* o0 = O + (size_t)r0*DM + h*DK;
    float* o1 = o0 + (size_t)8*DM;
    #pragma unroll
    for (int dt = 0; dt < 8; dt++) {
        const int c = dt*8 + 2*tg;
        float2 v0, v1;
        v0.x = to_tf32(oacc[dt][0]*inv0); v0.y = to_tf32(oacc[dt][1]*inv0);
        v1.x = to_tf32(oacc[dt][2]*inv1); v1.y = to_tf32(oacc[dt][3]*inv1);
        *(float2*)(o0 + c) = v0;
        *(float2*)(o1 + c) = v1;
    }
}

// ---------------------------------------------------------------------------
// Launch
// ---------------------------------------------------------------------------
extern "C" void kernel_launch(void* const* d_in, const int* in_sizes, int n_in,
                              void* d_out, int out_size)
{
    const float* x   = (const float*)d_in[0];
    const float* Wq  = (const float*)d_in[1];
    const float* bq  = (const float*)d_in[2];
    const float* Wk  = (const float*)d_in[3];
    const float* bk  = (const float*)d_in[4];
    const float* Wv  = (const float*)d_in[5];
    const float* bv  = (const float*)d_in[6];
    const float* Wo  = (const float*)d_in[7];
    const float* bo  = (const float*)d_in[8];
    const float* W1  = (const float*)d_in[9];
    const float* b1  = (const float*)d_in[10];
    const float* W2  = (const float*)d_in[11];
    const float* b2  = (const float*)d_in[12];
    const float* g1  = (const float*)d_in[13];
    const float* be1 = (const float*)d_in[14];
    const float* g2  = (const float*)d_in[15];
    const float* be2 = (const float*)d_in[16];
    float* out = (float*)d_out;

    float *p_h, *p_q, *p_k, *p_v, *p_o, *p_x1, *p_ff;
    float *p_wqt, *p_wkt, *p_wvt, *p_wot, *p_w1t, *p_w2t;
    cudaGetSymbolAddress((void**)&p_h,   g_h);
    cudaGetSymbolAddress((void**)&p_q,   g_q);
    cudaGetSymbolAddress((void**)&p_k,   g_k);
    cudaGetSymbolAddress((void**)&p_v,   g_v);
    cudaGetSymbolAddress((void**)&p_o,   g_o);
    cudaGetSymbolAddress((void**)&p_x1,  g_x1);
    cudaGetSymbolAddress((void**)&p_ff,  g_ff);
    cudaGetSymbolAddress((void**)&p_wqt, g_wqt);
    cudaGetSymbolAddress((void**)&p_wkt, g_wkt);
    cudaGetSymbolAddress((void**)&p_wvt, g_wvt);
    cudaGetSymbolAddress((void**)&p_wot, g_wot);
    cudaGetSymbolAddress((void**)&p_w1t, g_w1t);
    cudaGetSymbolAddress((void**)&p_w2t, g_w2t);

    static bool attr_set = false;
    if (!attr_set) {
        cudaFuncSetAttribute(mma_gemm<false,false,false>,
                             cudaFuncAttributeMaxDynamicSharedMemorySize, GEMM_SMEM);
        cudaFuncSetAttribute(mma_gemm<false,false,true>,
                             cudaFuncAttributeMaxDynamicSharedMemorySize, GEMM_SMEM);
        cudaFuncSetAttribute(mma_gemm<false,true,false>,
                             cudaFuncAttributeMaxDynamicSharedMemorySize, GEMM_SMEM);
        cudaFuncSetAttribute(mma_gemm<true,false,true>,
                             cudaFuncAttributeMaxDynamicSharedMemorySize, GEMM_SMEM);
        cudaFuncSetAttribute(fa_kernel,
                             cudaFuncAttributeMaxDynamicSharedMemorySize, ATT_SMEM);
        attr_set = true;
    }

    const dim3 tblk(32, 8);
    transpose_round<<<dim3(DM/32,  DM/32),  tblk>>>(Wq, p_wqt, DM,  DM);
    transpose_round<<<dim3(DM/32,  DM/32),  tblk>>>(Wk, p_wkt, DM,  DM);
    transpose_round<<<dim3(DM/32,  DM/32),  tblk>>>(Wv, p_wvt, DM,  DM);
    transpose_round<<<dim3(DM/32,  DM/32),  tblk>>>(Wo, p_wot, DM,  DM);
    transpose_round<<<dim3(DFF/32, DM/32),  tblk>>>(W1, p_w1t, DM,  DFF);
    transpose_round<<<dim3(DM/32,  DFF/32), tblk>>>(W2, p_w2t, DFF, DM);

    const dim3 gD (DM/128,  MROWS/128);   // (8, 64)
    const dim3 gF (DFF/128, MROWS/128);   // (32, 64)

    // 1. ln1(x) -> h (tf32-rounded)
    ln_kernel<<<MROWS, 256>>>(x, g1, be1, p_h);
    // 2-4. Q/K/V projections (tensor pipe; tf32-rounded outputs for attention)
    mma_gemm<false,false,true><<<gD, 256, GEMM_SMEM>>>(p_h, p_wqt, bq, nullptr, p_q, MROWS, DM, DM);
    mma_gemm<false,false,true><<<gD, 256, GEMM_SMEM>>>(p_h, p_wkt, bk, nullptr, p_k, MROWS, DM, DM);
    mma_gemm<false,false,true><<<gD, 256, GEMM_SMEM>>>(p_h, p_wvt, bv, nullptr, p_v, MROWS, DM, DM);
    // 5. causal attention (tensor pipe flash attention)
    fa_kernel<<<dim3(SS/64, BB*HH), 128, ATT_SMEM>>>(p_q, p_k, p_v, p_o);
    // 6. output projection + residual(x) -> x1
    mma_gemm<false,true,false><<<gD, 256, GEMM_SMEM>>>(p_o, p_wot, bo, x, p_x1, MROWS, DM, DM);
    // 7. ln2(x1) -> h (tf32-rounded)
    ln_kernel<<<MROWS, 256>>>(p_x1, g2, be2, p_h);
    // 8. FFN up + ReLU (tf32-rounded output)
    mma_gemm<true,false,true><<<gF, 256, GEMM_SMEM>>>(p_h, p_w1t, b1, nullptr, p_ff, MROWS, DFF, DM);
    // 9. FFN down + residual(x1) -> out
    mma_gemm<false,true,false><<<gD, 256, GEMM_SMEM>>>(p_ff, p_w2t, b2, p_x1, out, MROWS, DM, DFF);
}

// round 5
// speedup vs baseline: 11.0291x; 2.1701x over previous
#include <cuda_runtime.h>
#include <cuda_fp16.h>
#include <math.h>
#include <stdint.h>

// Problem dimensions (fixed by the reference)
#define BB    4
#define SS    2048
#define DM    1024
#define HH    16
#define DK    64
#define DFF   4096
#define MROWS (BB*SS)          // 8192
#define LN_EPS 1e-5f

// ---------------------------------------------------------------------------
// Scratch (device globals; no allocations allowed)
// ---------------------------------------------------------------------------
__device__ __half g_h  [MROWS*DM];    // ln1 / ln2 output (fp16)
__device__ __half g_q  [MROWS*DM];
__device__ __half g_k  [MROWS*DM];
__device__ __half g_v  [MROWS*DM];
__device__ __half g_o  [MROWS*DM];    // attention output (fp16)
__device__ float  g_x1 [MROWS*DM];    // residual after attention (fp32)
__device__ __half g_ff [MROWS*DFF];   // FFN hidden (fp16)
__device__ __half g_wqt[DM*DM];       // transposed fp16 weights [N,K]
__device__ __half g_wkt[DM*DM];
__device__ __half g_wvt[DM*DM];
__device__ __half g_wot[DM*DM];
__device__ __half g_w1t[DFF*DM];      // [4096,1024]
__device__ __half g_w2t[DM*DFF];      // [1024,4096]

// ---------------------------------------------------------------------------
// Helpers
// ---------------------------------------------------------------------------
__device__ __forceinline__ uint32_t smem_u32(const void* p) {
    uint32_t a;
    asm("{ .reg .u64 t; cvta.to.shared.u64 t, %1; cvt.u32.u64 %0, t; }"
        : "=r"(a) : "l"(p));
    return a;
}

__device__ __forceinline__ uint32_t pack_h2(float lo, float hi) {
    __half2 h = __floats2half2_rn(lo, hi);
    return *reinterpret_cast<uint32_t*>(&h);
}
__device__ __forceinline__ float rh(float x) {          // round to fp16 grid
    return __half2float(__float2half_rn(x));
}

#define CP_ASYNC16(dst, src) \
    asm volatile("cp.async.cg.shared.global [%0], [%1], 16;" :: "r"(dst), "l"(src))
#define CP_COMMIT()  asm volatile("cp.async.commit_group;" ::: "memory")
#define CP_WAIT(n)   asm volatile("cp.async.wait_group %0;" :: "n"(n) : "memory")

// m16n8k16 fp16 mma, fp32 accumulate (sm_80+ PTX)
#define MMA_F16(d, a, b0, b1) \
    asm volatile("mma.sync.aligned.m16n8k16.row.col.f32.f16.f16.f32 " \
        "{%0,%1,%2,%3}, {%4,%5,%6,%7}, {%8,%9}, {%0,%1,%2,%3};" \
        : "+f"(d[0]), "+f"(d[1]), "+f"(d[2]), "+f"(d[3]) \
        : "r"(a[0]), "r"(a[1]), "r"(a[2]), "r"(a[3]), "r"(b0), "r"(b1))

#define LDMATRIX_X4_TRANS(r0, r1, r2, r3, addr) \
    asm volatile("ldmatrix.sync.aligned.m8n8.x4.trans.shared.b16 {%0,%1,%2,%3}, [%4];" \
        : "=r"(r0), "=r"(r1), "=r"(r2), "=r"(r3) : "r"(addr))

// ---------------------------------------------------------------------------
// LayerNorm -> fp16 output (always a GEMM A operand)
// ---------------------------------------------------------------------------
__global__ __launch_bounds__(256) void ln_kernel(
    const float* __restrict__ X, const float* __restrict__ gamma,
    const float* __restrict__ beta, __half* __restrict__ out)
{
    const int row = blockIdx.x;
    const int t   = threadIdx.x;
    const float4 v = ((const float4*)(X + (size_t)row*DM))[t];

    float s  = v.x + v.y + v.z + v.w;
    float ss = v.x*v.x + v.y*v.y + v.z*v.z + v.w*v.w;

    #pragma unroll
    for (int o = 16; o > 0; o >>= 1) {
        s  += __shfl_xor_sync(0xffffffffu, s,  o);
        ss += __shfl_xor_sync(0xffffffffu, ss, o);
    }
    __shared__ float sh_s[8], sh_ss[8];
    const int w = t >> 5, lane = t & 31;
    if (lane == 0) { sh_s[w] = s; sh_ss[w] = ss; }
    __syncthreads();
    if (w == 0) {
        s  = (lane < 8) ? sh_s[lane]  : 0.f;
        ss = (lane < 8) ? sh_ss[lane] : 0.f;
        #pragma unroll
        for (int o = 4; o > 0; o >>= 1) {
            s  += __shfl_xor_sync(0xffffffffu, s,  o);
            ss += __shfl_xor_sync(0xffffffffu, ss, o);
        }
        if (lane == 0) { sh_s[0] = s; sh_ss[0] = ss; }
    }
    __syncthreads();
    s = sh_s[0]; ss = sh_ss[0];

    const float mu   = s * (1.0f / DM);
    const float var  = ss * (1.0f / DM) - mu*mu;
    const float rstd = rsqrtf(var + LN_EPS);

    const float4 g4 = ((const float4*)gamma)[t];
    const float4 b4 = ((const float4*)beta)[t];
    uint2 st;
    st.x = pack_h2((v.x - mu)*rstd*g4.x + b4.x, (v.y - mu)*rstd*g4.y + b4.y);
    st.y = pack_h2((v.z - mu)*rstd*g4.z + b4.z, (v.w - mu)*rstd*g4.w + b4.w);
    ((uint2*)(out + (size_t)row*DM))[t] = st;
}

// ---------------------------------------------------------------------------
// Weight transpose + fp16 rounding: W[K,N] (f32) -> Wt[N,K] (f16)
// ---------------------------------------------------------------------------
__global__ __launch_bounds__(256) void transpose_round(
    const float* __restrict__ W, __half* __restrict__ Wt, int K, int N)
{
    __shared__ float tile[32][33];
    const int tx = threadIdx.x, ty = threadIdx.y;
    const int n0 = blockIdx.x * 32, k0 = blockIdx.y * 32;
    #pragma unroll
    for (int i = ty; i < 32; i += 8)
        tile[i][tx] = W[(size_t)(k0 + i)*N + n0 + tx];
    __syncthreads();
    #pragma unroll
    for (int i = ty; i < 32; i += 8)
        Wt[(size_t)(n0 + i)*K + k0 + tx] = __float2half_rn(tile[tx][i]);
}

// ---------------------------------------------------------------------------
// fp16 mma.sync GEMM: C[M,N] = A[M,K] @ Bt[N,K]^T + bias (+relu)(+res)
// 128x128 CTA tile, BK=64 halves (128B rows), 3-stage cp.async, 256 threads.
// Warp grid 2(m) x 4(n): each warp 64x32, 4x4 m16n8k16 tiles (4 kk steps).
// SMEM rows padded to 72 halves (stride 36 banks = 4 mod 32 -> conflict-free).
// ---------------------------------------------------------------------------
#define GST    3
#define LDH    72
#define TILE_H (128*LDH)                 // halves per tile (9216)
#define STAGE_BYTES (2*TILE_H*2)         // A + B = 36864 B
#define GEMM_SMEM (GST*STAGE_BYTES)      // 110592 B

template<bool RELU, bool RES, bool HALF_OUT>
__global__ __launch_bounds__(256, 2) void mma_gemm(
    const __half* __restrict__ A, const __half* __restrict__ Bt,
    const float* __restrict__ bias, const float* __restrict__ res,
    void* __restrict__ Cv, int M, int N, int K)
{
    extern __shared__ char smc[];
    const uint32_t sm_b = smem_u32(smc);

    const int tid  = threadIdx.x;
    const int lane = tid & 31, wid = tid >> 5;
    const int wm = wid >> 2, wn = wid & 3;        // 2 x 4 warp grid
    const int gid = lane >> 2, tg = lane & 3;
    const int bx = blockIdx.x, by = blockIdx.y;

    const __half* Ab = A  + (size_t)by * 128 * K;
    const __half* Bb = Bt + (size_t)bx * 128 * K;
    const int nchunks = K >> 6;                   // K/64

    // Stage loader: 2 tiles x 128 rows x 64 halves (8x16B per row)
    auto load_stage = [&](int st, int kt) {
        const uint32_t a_dst = sm_b + (uint32_t)st*STAGE_BYTES;
        const uint32_t b_dst = a_dst + TILE_H*2;
        const __half* as = Ab + (size_t)kt*64;
        const __half* bs = Bb + (size_t)kt*64;
        #pragma unroll
        for (int it = 0; it < 4; it++) {
            const int idx = it*256 + tid;
            const int r = idx >> 3, c8 = idx & 7;
            const uint32_t off = (uint32_t)(r*144 + c8*16);
            CP_ASYNC16(a_dst + off, as + (size_t)r*K + c8*8);
            CP_ASYNC16(b_dst + off, bs + (size_t)r*K + c8*8);
        }
        CP_COMMIT();
    };

    float acc[4][4][4];
    #pragma unroll
    for (int i = 0; i < 4; i++)
        #pragma unroll
        for (int j = 0; j < 4; j++)
            #pragma unroll
            for (int k = 0; k < 4; k++) acc[i][j][k] = 0.f;

    load_stage(0, 0);
    if (nchunks > 1) load_stage(1, 1);

    for (int i = 0; i < nchunks; i++) {
        const int st = i % GST;
        if (i + 1 < nchunks) { CP_WAIT(1); } else { CP_WAIT(0); }
        __syncthreads();

        if (i + (GST-1) < nchunks)
            load_stage((i + GST - 1) % GST, i + GST - 1);

        const __half* as = (const __half*)(smc + (size_t)st*STAGE_BYTES);
        const __half* bs = as + TILE_H;

        #pragma unroll
        for (int kk = 0; kk < 4; kk++) {
            const int k0 = kk*16 + 2*tg;
            uint32_t a[4][4], b[4][2];
            #pragma unroll
            for (int mt = 0; mt < 4; mt++) {
                const int m0 = wm*64 + mt*16 + gid;
                a[mt][0] = *(const uint32_t*)(as + m0*LDH + k0);
                a[mt][1] = *(const uint32_t*)(as + (m0+8)*LDH + k0);
                a[mt][2] = *(const uint32_t*)(as + m0*LDH + k0 + 8);
                a[mt][3] = *(const uint32_t*)(as + (m0+8)*LDH + k0 + 8);
            }
            #pragma unroll
            for (int nt = 0; nt < 4; nt++) {
                const int n0 = wn*32 + nt*8 + gid;
                b[nt][0] = *(const uint32_t*)(bs + n0*LDH + k0);
                b[nt][1] = *(const uint32_t*)(bs + n0*LDH + k0 + 8);
            }
            #pragma unroll
            for (int mt = 0; mt < 4; mt++)
                #pragma unroll
                for (int nt = 0; nt < 4; nt++)
                    MMA_F16(acc[mt][nt], a[mt], b[nt][0], b[nt][1]);
        }
        __syncthreads();
    }

    // Epilogue
    #pragma unroll
    for (int mt = 0; mt < 4; mt++) {
        #pragma unroll
        for (int nt = 0; nt < 4; nt++) {
            const int r0 = by*128 + wm*64 + mt*16 + gid;
            const int c  = bx*128 + wn*32 + nt*8 + tg*2;
            const float2 b2 = *(const float2*)(bias + c);
            #pragma unroll
            for (int half_i = 0; half_i < 2; half_i++) {
                const int r = r0 + half_i*8;
                float ox = acc[mt][nt][half_i*2+0] + b2.x;
                float oy = acc[mt][nt][half_i*2+1] + b2.y;
                if (RELU) { ox = fmaxf(ox, 0.f); oy = fmaxf(oy, 0.f); }
                if (RES) {
                    const float2 r2 = *(const float2*)(res + (size_t)r*N + c);
                    ox += r2.x; oy += r2.y;
                }
                if (HALF_OUT) {
                    *(uint32_t*)((__half*)Cv + (size_t)r*N + c) = pack_h2(ox, oy);
                } else {
                    float2 o; o.x = ox; o.y = oy;
                    *(float2*)((float*)Cv + (size_t)r*N + c) = o;
                }
            }
        }
    }
}

// ---------------------------------------------------------------------------
// fp16 tensor-core causal flash attention, d_k=64.
// CTA: 128 threads (4 warps), 64 q rows (16/warp), 64-key KV tiles,
// double-buffered cp.async. S scaled post-MMA (x0.125 exact). P packed to
// half2 straight from accumulator layout; V B-frags via ldmatrix.x4.trans.
// ---------------------------------------------------------------------------
#define ALDH 72
#define ATILE_B (64*ALDH*2)               // 9216 B per 64x64 half tile
#define ATT_SMEM (4*ATILE_B)              // 2 stages x (K+V) = 36864 B

__global__ __launch_bounds__(128) void fa_kernel(
    const __half* __restrict__ Q, const __half* __restrict__ K,
    const __half* __restrict__ V, __half* __restrict__ O)
{
    extern __shared__ char fsc[];
    const int tid  = threadIdx.x;
    const int lane = tid & 31, w = tid >> 5;
    const int gid  = lane >> 2, tg = lane & 3;
    const int qt   = (int)gridDim.x - 1 - (int)blockIdx.x;   // big tiles first
    const int bh   = blockIdx.y;
    const int b    = bh >> 4, h = bh & 15;
    const int qbase = qt * 64;

    __half* Ks[2] = { (__half*)fsc,                 (__half*)(fsc + 2*ATILE_B) };
    __half* Vs[2] = { (__half*)(fsc + ATILE_B),     (__half*)(fsc + 3*ATILE_B) };

    auto load_tile = [&](__half* dst, const __half* src) {
        const uint32_t d0 = smem_u32(dst);
        #pragma unroll
        for (int i = 0; i < 4; i++) {
            const int idx = i*128 + tid;
            const int r = idx >> 3, c8 = idx & 7;
            CP_ASYNC16(d0 + (uint32_t)(r*144 + c8*16), src + (size_t)r*DM + c8*8);
        }
    };

    const __half* Kg = K + ((size_t)(b*SS))*DM + h*DK;
    const __half* Vg = V + ((size_t)(b*SS))*DM + h*DK;
    auto load_kv = [&](int st, int kt) {
        load_tile(Ks[st], Kg + (size_t)(kt*64)*DM);
        load_tile(Vs[st], Vg + (size_t)(kt*64)*DM);
        CP_COMMIT();
    };

    // --- Stage Q through smem, grab fp16 A fragments ---
    load_tile(Ks[0], Q + ((size_t)(b*SS + qbase))*DM + h*DK);
    CP_COMMIT();
    CP_WAIT(0);
    __syncthreads();

    uint32_t qf[4][4];
    {
        const __half* qs = Ks[0];
        const int m0 = w*16 + gid;
        #pragma unroll
        for (int kk = 0; kk < 4; kk++) {
            const int k0 = kk*16 + 2*tg;
            qf[kk][0] = *(const uint32_t*)(qs + m0*ALDH + k0);
            qf[kk][1] = *(const uint32_t*)(qs + (m0+8)*ALDH + k0);
            qf[kk][2] = *(const uint32_t*)(qs + m0*ALDH + k0 + 8);
            qf[kk][3] = *(const uint32_t*)(qs + (m0+8)*ALDH + k0 + 8);
        }
    }
    __syncthreads();

    load_kv(0, 0);
    if (qt >= 1) load_kv(1, 1);

    float oacc[8][4];
    #pragma unroll
    for (int d = 0; d < 8; d++) {
        oacc[d][0] = 0.f; oacc[d][1] = 0.f; oacc[d][2] = 0.f; oacc[d][3] = 0.f;
    }
    float m0r = -INFINITY, m1r = -INFINITY, l0 = 0.f, l1 = 0.f;

    for (int kt = 0; kt <= qt; kt++) {
        const int st = kt & 1;
        if (kt < qt) { CP_WAIT(1); } else { CP_WAIT(0); }
        __syncthreads();
        const __half* ks = Ks[st];
        const __half* vs = Vs[st];
        const uint32_t vs_b = smem_u32(vs);

        // ---- S = Q K^T ----
        float sacc[8][4];
        #pragma unroll
        for (int nt = 0; nt < 8; nt++) {
            sacc[nt][0] = 0.f; sacc[nt][1] = 0.f; sacc[nt][2] = 0.f; sacc[nt][3] = 0.f;
        }
        #pragma unroll
        for (int kk = 0; kk < 4; kk++) {
            const int k0 = kk*16 + 2*tg;
            #pragma unroll
            for (int nt = 0; nt < 8; nt++) {
                const uint32_t b0 = *(const uint32_t*)(ks + (nt*8+gid)*ALDH + k0);
                const uint32_t b1 = *(const uint32_t*)(ks + (nt*8+gid)*ALDH + k0 + 8);
                MMA_F16(sacc[nt], qf[kk], b0, b1);
            }
        }
        #pragma unroll
        for (int nt = 0; nt < 8; nt++) {
            sacc[nt][0] *= 0.125f; sacc[nt][1] *= 0.125f;
            sacc[nt][2] *= 0.125f; sacc[nt][3] *= 0.125f;
        }

        // ---- causal mask (diagonal tile only) ----
        if (kt == qt) {
            const int q0 = w*16 + gid;
            #pragma unroll
            for (int nt = 0; nt < 8; nt++) {
                const int s0 = nt*8 + 2*tg;
                if (s0     > q0)     sacc[nt][0] = -1e30f;
                if (s0 + 1 > q0)     sacc[nt][1] = -1e30f;
                if (s0     > q0 + 8) sacc[nt][2] = -1e30f;
                if (s0 + 1 > q0 + 8) sacc[nt][3] = -1e30f;
            }
        }

        // ---- online softmax ----
        float t0 = -1e30f, t1 = -1e30f;
        #pragma unroll
        for (int nt = 0; nt < 8; nt++) {
            t0 = fmaxf(t0, fmaxf(sacc[nt][0], sacc[nt][1]));
            t1 = fmaxf(t1, fmaxf(sacc[nt][2], sacc[nt][3]));
        }
        t0 = fmaxf(t0, __shfl_xor_sync(0xffffffffu, t0, 1));
        t0 = fmaxf(t0, __shfl_xor_sync(0xffffffffu, t0, 2));
        t1 = fmaxf(t1, __shfl_xor_sync(0xffffffffu, t1, 1));
        t1 = fmaxf(t1, __shfl_xor_sync(0xffffffffu, t1, 2));

        const float mn0 = fmaxf(m0r, t0), mn1 = fmaxf(m1r, t1);
        const float cr0 = __expf(m0r - mn0), cr1 = __expf(m1r - mn1);
        m0r = mn0; m1r = mn1;
        l0 *= cr0; l1 *= cr1;
        #pragma unroll
        for (int d = 0; d < 8; d++) {
            oacc[d][0] *= cr0; oacc[d][1] *= cr0;
            oacc[d][2] *= cr1; oacc[d][3] *= cr1;
        }

        float s0 = 0.f, s1 = 0.f;
        #pragma unroll
        for (int nt = 0; nt < 8; nt++) {
            const float p0 = rh(__expf(sacc[nt][0] - mn0));
            const float p1 = rh(__expf(sacc[nt][1] - mn0));
            const float p2 = rh(__expf(sacc[nt][2] - mn1));
            const float p3 = rh(__expf(sacc[nt][3] - mn1));
            s0 += p0 + p1; s1 += p2 + p3;
            sacc[nt][0] = p0; sacc[nt][1] = p1; sacc[nt][2] = p2; sacc[nt][3] = p3;
        }
        s0 += __shfl_xor_sync(0xffffffffu, s0, 1);
        s0 += __shfl_xor_sync(0xffffffffu, s0, 2);
        s1 += __shfl_xor_sync(0xffffffffu, s1, 1);
        s1 += __shfl_xor_sync(0xffffffffu, s1, 2);
        l0 += s0; l1 += s1;

        // ---- O += P V ----
        const int lm = lane >> 3, lr = lane & 7;      // ldmatrix addressing
        #pragma unroll
        for (int j = 0; j < 4; j++) {
            uint32_t a[4];
            a[0] = pack_h2(sacc[2*j  ][0], sacc[2*j  ][1]);
            a[1] = pack_h2(sacc[2*j  ][2], sacc[2*j  ][3]);
            a[2] = pack_h2(sacc[2*j+1][0], sacc[2*j+1][1]);
            a[3] = pack_h2(sacc[2*j+1][2], sacc[2*j+1][3]);
            #pragma unroll
            for (int dtp = 0; dtp < 4; dtp++) {
                const int s_a = j*16 + ((lm & 1) << 3) + lr;
                const int d_a = dtp*16 + ((lm >> 1) << 3);
                const uint32_t addr = vs_b + (uint32_t)(s_a*ALDH + d_a)*2;
                uint32_t b0, b1, b2, b3;
                LDMATRIX_X4_TRANS(b0, b1, b2, b3, addr);
                MMA_F16(oacc[dtp*2],   a, b0, b1);
                MMA_F16(oacc[dtp*2+1], a, b2, b3);
            }
        }
        __syncthreads();

        if (kt + 2 <= qt) load_kv(st, kt + 2);
    }

    // ---- normalize + write (fp16; feeds Wo GEMM) ----
    const float inv0 = 1.0f / l0, inv1 = 1.0f / l1;
    const int r0 = b*SS + qbase + w*16 + gid;
    __half* o0 = O + (size_t)r0*DM + h*DK;
    __half* o1 = o0 + (size_t)8*DM;
    #pragma unroll
    for (int dt = 0; dt < 8; dt++) {
        const int c = dt*8 + 2*tg;
        *(uint32_t*)(o0 + c) = pack_h2(oacc[dt][0]*inv0, oacc[dt][1]*inv0);
        *(uint32_t*)(o1 + c) = pack_h2(oacc[dt][2]*inv1, oacc[dt][3]*inv1);
    }
}

// ---------------------------------------------------------------------------
// Launch
// ---------------------------------------------------------------------------
extern "C" void kernel_launch(void* const* d_in, const int* in_sizes, int n_in,
                              void* d_out, int out_size)
{
    const float* x   = (const float*)d_in[0];
    const float* Wq  = (const float*)d_in[1];
    const float* bq  = (const float*)d_in[2];
    const float* Wk  = (const float*)d_in[3];
    const float* bk  = (const float*)d_in[4];
    const float* Wv  = (const float*)d_in[5];
    const float* bv  = (const float*)d_in[6];
    const float* Wo  = (const float*)d_in[7];
    const float* bo  = (const float*)d_in[8];
    const float* W1  = (const float*)d_in[9];
    const float* b1  = (const float*)d_in[10];
    const float* W2  = (const float*)d_in[11];
    const float* b2  = (const float*)d_in[12];
    const float* g1  = (const float*)d_in[13];
    const float* be1 = (const float*)d_in[14];
    const float* g2  = (const float*)d_in[15];
    const float* be2 = (const float*)d_in[16];
    float* out = (float*)d_out;

    __half *p_h, *p_q, *p_k, *p_v, *p_o, *p_ff;
    __half *p_wqt, *p_wkt, *p_wvt, *p_wot, *p_w1t, *p_w2t;
    float  *p_x1;
    cudaGetSymbolAddress((void**)&p_h,   g_h);
    cudaGetSymbolAddress((void**)&p_q,   g_q);
    cudaGetSymbolAddress((void**)&p_k,   g_k);
    cudaGetSymbolAddress((void**)&p_v,   g_v);
    cudaGetSymbolAddress((void**)&p_o,   g_o);
    cudaGetSymbolAddress((void**)&p_x1,  g_x1);
    cudaGetSymbolAddress((void**)&p_ff,  g_ff);
    cudaGetSymbolAddress((void**)&p_wqt, g_wqt);
    cudaGetSymbolAddress((void**)&p_wkt, g_wkt);
    cudaGetSymbolAddress((void**)&p_wvt, g_wvt);
    cudaGetSymbolAddress((void**)&p_wot, g_wot);
    cudaGetSymbolAddress((void**)&p_w1t, g_w1t);
    cudaGetSymbolAddress((void**)&p_w2t, g_w2t);

    static bool attr_set = false;
    if (!attr_set) {
        cudaFuncSetAttribute(mma_gemm<false,false,true>,
                             cudaFuncAttributeMaxDynamicSharedMemorySize, GEMM_SMEM);
        cudaFuncSetAttribute(mma_gemm<false,true,false>,
                             cudaFuncAttributeMaxDynamicSharedMemorySize, GEMM_SMEM);
        cudaFuncSetAttribute(mma_gemm<true,false,true>,
                             cudaFuncAttributeMaxDynamicSharedMemorySize, GEMM_SMEM);
        cudaFuncSetAttribute(fa_kernel,
                             cudaFuncAttributeMaxDynamicSharedMemorySize, ATT_SMEM);
        attr_set = true;
    }

    const dim3 tblk(32, 8);
    transpose_round<<<dim3(DM/32,  DM/32),  tblk>>>(Wq, p_wqt, DM,  DM);
    transpose_round<<<dim3(DM/32,  DM/32),  tblk>>>(Wk, p_wkt, DM,  DM);
    transpose_round<<<dim3(DM/32,  DM/32),  tblk>>>(Wv, p_wvt, DM,  DM);
    transpose_round<<<dim3(DM/32,  DM/32),  tblk>>>(Wo, p_wot, DM,  DM);
    transpose_round<<<dim3(DFF/32, DM/32),  tblk>>>(W1, p_w1t, DM,  DFF);
    transpose_round<<<dim3(DM/32,  DFF/32), tblk>>>(W2, p_w2t, DFF, DM);

    const dim3 gD (DM/128,  MROWS/128);   // (8, 64)
    const dim3 gF (DFF/128, MROWS/128);   // (32, 64)

    // 1. ln1(x) -> h (fp16)
    ln_kernel<<<MROWS, 256>>>(x, g1, be1, p_h);
    // 2-4. Q/K/V projections (fp16 tensor pipe)
    mma_gemm<false,false,true><<<gD, 256, GEMM_SMEM>>>(p_h, p_wqt, bq, nullptr, p_q, MROWS, DM, DM);
    mma_gemm<false,false,true><<<gD, 256, GEMM_SMEM>>>(p_h, p_wkt, bk, nullptr, p_k, MROWS, DM, DM);
    mma_gemm<false,false,true><<<gD, 256, GEMM_SMEM>>>(p_h, p_wvt, bv, nullptr, p_v, MROWS, DM, DM);
    // 5. causal attention (fp16 flash attention)
    fa_kernel<<<dim3(SS/64, BB*HH), 128, ATT_SMEM>>>(p_q, p_k, p_v, p_o);
    // 6. output projection + residual(x) -> x1 (fp32)
    mma_gemm<false,true,false><<<gD, 256, GEMM_SMEM>>>(p_o, p_wot, bo, x, p_x1, MROWS, DM, DM);
    // 7. ln2(x1) -> h (fp16)
    ln_kernel<<<MROWS, 256>>>(p_x1, g2, be2, p_h);
    // 8. FFN up + ReLU (fp16 out)
    mma_gemm<true,false,true><<<gF, 256, GEMM_SMEM>>>(p_h, p_w1t, b1, nullptr, p_ff, MROWS, DFF, DM);
    // 9. FFN down + residual(x1) -> out (fp32)
    mma_gemm<false,true,false><<<gD, 256, GEMM_SMEM>>>(p_ff, p_w2t, b2, p_x1, out, MROWS, DM, DFF);
}

// round 6
// speedup vs baseline: 11.5449x; 1.0468x over previous
#include <cuda_runtime.h>
#include <cuda_fp16.h>
#include <math.h>
#include <stdint.h>

// Problem dimensions (fixed by the reference)
#define BB    4
#define SS    2048
#define DM    1024
#define HH    16
#define DK    64
#define DFF   4096
#define MROWS (BB*SS)          // 8192
#define LN_EPS 1e-5f

// ---------------------------------------------------------------------------
// Scratch (device globals; no allocations allowed)
// ---------------------------------------------------------------------------
__device__ __half g_h  [MROWS*DM];    // ln1 / ln2 output (fp16)
__device__ __half g_q  [MROWS*DM];
__device__ __half g_k  [MROWS*DM];
__device__ __half g_v  [MROWS*DM];
__device__ __half g_o  [MROWS*DM];    // attention output (fp16)
__device__ float  g_x1 [MROWS*DM];    // residual after attention (fp32)
__device__ __half g_ff [MROWS*DFF];   // FFN hidden (fp16)
__device__ __half g_wqt[DM*DM];       // transposed fp16 weights [N,K]
__device__ __half g_wkt[DM*DM];
__device__ __half g_wvt[DM*DM];
__device__ __half g_wot[DM*DM];
__device__ __half g_w1t[DFF*DM];      // [4096,1024]
__device__ __half g_w2t[DM*DFF];      // [1024,4096]

// ---------------------------------------------------------------------------
// Helpers
// ---------------------------------------------------------------------------
__device__ __forceinline__ uint32_t smem_u32(const void* p) {
    uint32_t a;
    asm("{ .reg .u64 t; cvta.to.shared.u64 t, %1; cvt.u32.u64 %0, t; }"
        : "=r"(a) : "l"(p));
    return a;
}

__device__ __forceinline__ uint32_t pack_h2(float lo, float hi) {
    __half2 h = __floats2half2_rn(lo, hi);
    return *reinterpret_cast<uint32_t*>(&h);
}

__device__ __forceinline__ float ex2(float x) {        // 2^x, MUFU.EX2
    float y;
    asm("ex2.approx.f32 %0, %1;" : "=f"(y) : "f"(x));
    return y;
}

#define CP_ASYNC16(dst, src) \
    asm volatile("cp.async.cg.shared.global [%0], [%1], 16;" :: "r"(dst), "l"(src))
#define CP_COMMIT()  asm volatile("cp.async.commit_group;" ::: "memory")
#define CP_WAIT(n)   asm volatile("cp.async.wait_group %0;" :: "n"(n) : "memory")

// m16n8k16 fp16 mma, fp32 accumulate (sm_80+ PTX)
#define MMA_F16(d, a, b0, b1) \
    asm volatile("mma.sync.aligned.m16n8k16.row.col.f32.f16.f16.f32 " \
        "{%0,%1,%2,%3}, {%4,%5,%6,%7}, {%8,%9}, {%0,%1,%2,%3};" \
        : "+f"(d[0]), "+f"(d[1]), "+f"(d[2]), "+f"(d[3]) \
        : "r"(a[0]), "r"(a[1]), "r"(a[2]), "r"(a[3]), "r"(b0), "r"(b1))

#define LDSM_X4(r0, r1, r2, r3, addr) \
    asm volatile("ldmatrix.sync.aligned.m8n8.x4.shared.b16 {%0,%1,%2,%3}, [%4];" \
        : "=r"(r0), "=r"(r1), "=r"(r2), "=r"(r3) : "r"(addr))

#define LDSM_X2(r0, r1, addr) \
    asm volatile("ldmatrix.sync.aligned.m8n8.x2.shared.b16 {%0,%1}, [%2];" \
        : "=r"(r0), "=r"(r1) : "r"(addr))

#define LDSM_X4_TRANS(r0, r1, r2, r3, addr) \
    asm volatile("ldmatrix.sync.aligned.m8n8.x4.trans.shared.b16 {%0,%1,%2,%3}, [%4];" \
        : "=r"(r0), "=r"(r1), "=r"(r2), "=r"(r3) : "r"(addr))

// ---------------------------------------------------------------------------
// LayerNorm -> fp16 output (always a GEMM A operand)
// ---------------------------------------------------------------------------
__global__ __launch_bounds__(256) void ln_kernel(
    const float* __restrict__ X, const float* __restrict__ gamma,
    const float* __restrict__ beta, __half* __restrict__ out)
{
    const int row = blockIdx.x;
    const int t   = threadIdx.x;
    const float4 v = ((const float4*)(X + (size_t)row*DM))[t];

    float s  = v.x + v.y + v.z + v.w;
    float ss = v.x*v.x + v.y*v.y + v.z*v.z + v.w*v.w;

    #pragma unroll
    for (int o = 16; o > 0; o >>= 1) {
        s  += __shfl_xor_sync(0xffffffffu, s,  o);
        ss += __shfl_xor_sync(0xffffffffu, ss, o);
    }
    __shared__ float sh_s[8], sh_ss[8];
    const int w = t >> 5, lane = t & 31;
    if (lane == 0) { sh_s[w] = s; sh_ss[w] = ss; }
    __syncthreads();
    if (w == 0) {
        s  = (lane < 8) ? sh_s[lane]  : 0.f;
        ss = (lane < 8) ? sh_ss[lane] : 0.f;
        #pragma unroll
        for (int o = 4; o > 0; o >>= 1) {
            s  += __shfl_xor_sync(0xffffffffu, s,  o);
            ss += __shfl_xor_sync(0xffffffffu, ss, o);
        }
        if (lane == 0) { sh_s[0] = s; sh_ss[0] = ss; }
    }
    __syncthreads();
    s = sh_s[0]; ss = sh_ss[0];

    const float mu   = s * (1.0f / DM);
    const float var  = ss * (1.0f / DM) - mu*mu;
    const float rstd = rsqrtf(var + LN_EPS);

    const float4 g4 = ((const float4*)gamma)[t];
    const float4 b4 = ((const float4*)beta)[t];
    uint2 st;
    st.x = pack_h2((v.x - mu)*rstd*g4.x + b4.x, (v.y - mu)*rstd*g4.y + b4.y);
    st.y = pack_h2((v.z - mu)*rstd*g4.z + b4.z, (v.w - mu)*rstd*g4.w + b4.w);
    ((uint2*)(out + (size_t)row*DM))[t] = st;
}

// ---------------------------------------------------------------------------
// Weight transpose + fp16 rounding: W[K,N] (f32) -> Wt[N,K] (f16)
// ---------------------------------------------------------------------------
__global__ __launch_bounds__(256) void transpose_round(
    const float* __restrict__ W, __half* __restrict__ Wt, int K, int N)
{
    __shared__ float tile[32][33];
    const int tx = threadIdx.x, ty = threadIdx.y;
    const int n0 = blockIdx.x * 32, k0 = blockIdx.y * 32;
    #pragma unroll
    for (int i = ty; i < 32; i += 8)
        tile[i][tx] = W[(size_t)(k0 + i)*N + n0 + tx];
    __syncthreads();
    #pragma unroll
    for (int i = ty; i < 32; i += 8)
        Wt[(size_t)(n0 + i)*K + k0 + tx] = __float2half_rn(tile[tx][i]);
}

// Four DMxDM transposes in one launch (z selects the pair)
__global__ __launch_bounds__(256) void transpose_round4(
    const float* __restrict__ W0, const float* __restrict__ W1,
    const float* __restrict__ W2, const float* __restrict__ W3,
    __half* __restrict__ T0, __half* __restrict__ T1,
    __half* __restrict__ T2, __half* __restrict__ T3)
{
    const float* W; __half* T;
    switch (blockIdx.z) {
        case 0: W = W0; T = T0; break;
        case 1: W = W1; T = T1; break;
        case 2: W = W2; T = T2; break;
        default: W = W3; T = T3; break;
    }
    __shared__ float tile[32][33];
    const int tx = threadIdx.x, ty = threadIdx.y;
    const int n0 = blockIdx.x * 32, k0 = blockIdx.y * 32;
    #pragma unroll
    for (int i = ty; i < 32; i += 8)
        tile[i][tx] = W[(size_t)(k0 + i)*DM + n0 + tx];
    __syncthreads();
    #pragma unroll
    for (int i = ty; i < 32; i += 8)
        T[(size_t)(n0 + i)*DM + k0 + tx] = __float2half_rn(tile[tx][i]);
}

// ---------------------------------------------------------------------------
// fp16 mma.sync GEMM: C[M,N] = A[M,K] @ Bt[N,K]^T + bias (+relu)(+res)
// 128x128 CTA tile, BK=64 halves, 3-stage cp.async, 256 threads (8 warps).
// Fragments via ldmatrix (A x4, B x2); SMEM rows padded to 72 halves.
// ---------------------------------------------------------------------------
#define GST    3
#define LDH    72
#define TILE_H (128*LDH)                 // halves per tile (9216)
#define STAGE_BYTES (2*TILE_H*2)         // A + B = 36864 B
#define GEMM_SMEM (GST*STAGE_BYTES)      // 110592 B

template<bool RELU, bool RES, bool HALF_OUT>
__global__ __launch_bounds__(256, 2) void mma_gemm(
    const __half* __restrict__ A, const __half* __restrict__ Bt,
    const float* __restrict__ bias, const float* __restrict__ res,
    void* __restrict__ Cv, int M, int N, int K)
{
    extern __shared__ char smc[];
    const uint32_t sm_b = smem_u32(smc);

    const int tid  = threadIdx.x;
    const int lane = tid & 31, wid = tid >> 5;
    const int wm = wid >> 2, wn = wid & 3;        // 2 x 4 warp grid
    const int gid = lane >> 2, tg = lane & 3;
    const int bx = blockIdx.x, by = blockIdx.y;

    const __half* Ab = A  + (size_t)by * 128 * K;
    const __half* Bb = Bt + (size_t)bx * 128 * K;
    const int nchunks = K >> 6;                   // K/64

    // ldmatrix per-lane offsets (bytes) within a stage's A / B tile
    const int la7 = lane & 7;
    uint32_t offA[4], offB[4];
    {
        const int arow = la7 + ((lane >> 3) & 1) * 8;
        const int acol = (lane >> 4) * 8;
        #pragma unroll
        for (int mt = 0; mt < 4; mt++)
            offA[mt] = (uint32_t)(((wm*64 + mt*16 + arow)*LDH + acol) * 2);
        const int bcol = ((lane >> 3) & 1) * 8;
        #pragma unroll
        for (int nt = 0; nt < 4; nt++)
            offB[nt] = (uint32_t)(((wn*32 + nt*8 + la7)*LDH + bcol) * 2);
    }

    // Stage loader: 2 tiles x 128 rows x 64 halves (8x16B per row)
    auto load_stage = [&](int st, int kt) {
        const uint32_t a_dst = sm_b + (uint32_t)st*STAGE_BYTES;
        const uint32_t b_dst = a_dst + TILE_H*2;
        const __half* as = Ab + (size_t)kt*64;
        const __half* bs = Bb + (size_t)kt*64;
        #pragma unroll
        for (int it = 0; it < 4; it++) {
            const int idx = it*256 + tid;
            const int r = idx >> 3, c8 = idx & 7;
            const uint32_t off = (uint32_t)(r*144 + c8*16);
            CP_ASYNC16(a_dst + off, as + (size_t)r*K + c8*8);
            CP_ASYNC16(b_dst + off, bs + (size_t)r*K + c8*8);
        }
        CP_COMMIT();
    };

    float acc[4][4][4];
    #pragma unroll
    for (int i = 0; i < 4; i++)
        #pragma unroll
        for (int j = 0; j < 4; j++)
            #pragma unroll
            for (int k = 0; k < 4; k++) acc[i][j][k] = 0.f;

    load_stage(0, 0);
    if (nchunks > 1) load_stage(1, 1);

    for (int i = 0; i < nchunks; i++) {
        const int st = i % GST;
        if (i + 1 < nchunks) { CP_WAIT(1); } else { CP_WAIT(0); }
        __syncthreads();

        if (i + (GST-1) < nchunks)
            load_stage((i + GST - 1) % GST, i + GST - 1);

        const uint32_t aBase = sm_b + (uint32_t)st*STAGE_BYTES;
        const uint32_t bBase = aBase + TILE_H*2;

        #pragma unroll
        for (int kk = 0; kk < 4; kk++) {
            uint32_t a[4][4], b[4][2];
            #pragma unroll
            for (int mt = 0; mt < 4; mt++)
                LDSM_X4(a[mt][0], a[mt][1], a[mt][2], a[mt][3],
                        aBase + offA[mt] + kk*32);
            #pragma unroll
            for (int nt = 0; nt < 4; nt++)
                LDSM_X2(b[nt][0], b[nt][1], bBase + offB[nt] + kk*32);
            #pragma unroll
            for (int mt = 0; mt < 4; mt++)
                #pragma unroll
                for (int nt = 0; nt < 4; nt++)
                    MMA_F16(acc[mt][nt], a[mt], b[nt][0], b[nt][1]);
        }
        __syncthreads();
    }

    // Epilogue
    #pragma unroll
    for (int mt = 0; mt < 4; mt++) {
        #pragma unroll
        for (int nt = 0; nt < 4; nt++) {
            const int r0 = by*128 + wm*64 + mt*16 + gid;
            const int c  = bx*128 + wn*32 + nt*8 + tg*2;
            const float2 b2 = *(const float2*)(bias + c);
            #pragma unroll
            for (int half_i = 0; half_i < 2; half_i++) {
                const int r = r0 + half_i*8;
                float ox = acc[mt][nt][half_i*2+0] + b2.x;
                float oy = acc[mt][nt][half_i*2+1] + b2.y;
                if (RELU) { ox = fmaxf(ox, 0.f); oy = fmaxf(oy, 0.f); }
                if (RES) {
                    const float2 r2 = *(const float2*)(res + (size_t)r*N + c);
                    ox += r2.x; oy += r2.y;
                }
                if (HALF_OUT) {
                    *(uint32_t*)((__half*)Cv + (size_t)r*N + c) = pack_h2(ox, oy);
                } else {
                    float2 o; o.x = ox; o.y = oy;
                    *(float2*)((float*)Cv + (size_t)r*N + c) = o;
                }
            }
        }
    }
}

// ---------------------------------------------------------------------------
// fp16 tensor-core causal flash attention, d_k=64.
// CTA: 128 threads (4 warps), 64 q rows (16/warp), 64-key KV tiles,
// double-buffered cp.async. Softmax in exp2 domain with the 1/sqrt(dk)
// scale folded into one FFMA. K/Q frags via ldmatrix; V via ldmatrix.trans.
// ---------------------------------------------------------------------------
#define ALDH 72
#define ATILE_B (64*ALDH*2)               // 9216 B per 64x64 half tile
#define ATT_SMEM (4*ATILE_B)              // 2 stages x (K+V) = 36864 B
#define FA_C1 0.1803368801111204f          // log2(e)/8

__global__ __launch_bounds__(128) void fa_kernel(
    const __half* __restrict__ Q, const __half* __restrict__ K,
    const __half* __restrict__ V, __half* __restrict__ O)
{
    extern __shared__ char fsc[];
    const int tid  = threadIdx.x;
    const int lane = tid & 31, w = tid >> 5;
    const int gid  = lane >> 2, tg = lane & 3;
    const int qt   = (int)gridDim.x - 1 - (int)blockIdx.x;   // big tiles first
    const int bh   = blockIdx.y;
    const int b    = bh >> 4, h = bh & 15;
    const int qbase = qt * 64;

    __half* Ks[2] = { (__half*)fsc,                 (__half*)(fsc + 2*ATILE_B) };
    __half* Vs[2] = { (__half*)(fsc + ATILE_B),     (__half*)(fsc + 3*ATILE_B) };

    auto load_tile = [&](__half* dst, const __half* src) {
        const uint32_t d0 = smem_u32(dst);
        #pragma unroll
        for (int i = 0; i < 4; i++) {
            const int idx = i*128 + tid;
            const int r = idx >> 3, c8 = idx & 7;
            CP_ASYNC16(d0 + (uint32_t)(r*144 + c8*16), src + (size_t)r*DM + c8*8);
        }
    };

    const __half* Kg = K + ((size_t)(b*SS))*DM + h*DK;
    const __half* Vg = V + ((size_t)(b*SS))*DM + h*DK;
    auto load_kv = [&](int st, int kt) {
        load_tile(Ks[st], Kg + (size_t)(kt*64)*DM);
        load_tile(Vs[st], Vg + (size_t)(kt*64)*DM);
        CP_COMMIT();
    };

    // ldmatrix per-lane offsets
    const int la7 = lane & 7;
    const uint32_t offQ = (uint32_t)(((w*16 + la7 + ((lane>>3)&1)*8)*ALDH
                                     + (lane>>4)*8) * 2);
    uint32_t offK[8];
    #pragma unroll
    for (int nt = 0; nt < 8; nt++)
        offK[nt] = (uint32_t)(((nt*8 + la7)*ALDH + ((lane>>3)&1)*8) * 2);

    // --- Stage Q through smem, grab fp16 A fragments ---
    load_tile(Ks[0], Q + ((size_t)(b*SS + qbase))*DM + h*DK);
    CP_COMMIT();
    CP_WAIT(0);
    __syncthreads();

    uint32_t qf[4][4];
    {
        const uint32_t qsB = smem_u32(Ks[0]);
        #pragma unroll
        for (int kk = 0; kk < 4; kk++)
            LDSM_X4(qf[kk][0], qf[kk][1], qf[kk][2], qf[kk][3],
                    qsB + offQ + kk*32);
    }
    __syncthreads();

    load_kv(0, 0);
    if (qt >= 1) load_kv(1, 1);

    float oacc[8][4];
    #pragma unroll
    for (int d = 0; d < 8; d++) {
        oacc[d][0] = 0.f; oacc[d][1] = 0.f; oacc[d][2] = 0.f; oacc[d][3] = 0.f;
    }
    float m0r = -INFINITY, m1r = -INFINITY, l0 = 0.f, l1 = 0.f;

    for (int kt = 0; kt <= qt; kt++) {
        const int st = kt & 1;
        if (kt < qt) { CP_WAIT(1); } else { CP_WAIT(0); }
        __syncthreads();
        const uint32_t ks_b = smem_u32(Ks[st]);
        const uint32_t vs_b = smem_u32(Vs[st]);

        // ---- S = Q K^T (unscaled) ----
        float sacc[8][4];
        #pragma unroll
        for (int nt = 0; nt < 8; nt++) {
            sacc[nt][0] = 0.f; sacc[nt][1] = 0.f; sacc[nt][2] = 0.f; sacc[nt][3] = 0.f;
        }
        #pragma unroll
        for (int kk = 0; kk < 4; kk++) {
            #pragma unroll
            for (int nt = 0; nt < 8; nt++) {
                uint32_t b0, b1;
                LDSM_X2(b0, b1, ks_b + offK[nt] + kk*32);
                MMA_F16(sacc[nt], qf[kk], b0, b1);
            }
        }

        // ---- causal mask (diagonal tile only) ----
        if (kt == qt) {
            const int q0 = w*16 + gid;
            #pragma unroll
            for (int nt = 0; nt < 8; nt++) {
                const int s0 = nt*8 + 2*tg;
                if (s0     > q0)     sacc[nt][0] = -1e30f;
                if (s0 + 1 > q0)     sacc[nt][1] = -1e30f;
                if (s0     > q0 + 8) sacc[nt][2] = -1e30f;
                if (s0 + 1 > q0 + 8) sacc[nt][3] = -1e30f;
            }
        }

        // ---- online softmax in exp2 domain (scale folded into FFMA) ----
        float t0 = -1e30f, t1 = -1e30f;
        #pragma unroll
        for (int nt = 0; nt < 8; nt++) {
            t0 = fmaxf(t0, fmaxf(sacc[nt][0], sacc[nt][1]));
            t1 = fmaxf(t1, fmaxf(sacc[nt][2], sacc[nt][3]));
        }
        t0 = fmaxf(t0, __shfl_xor_sync(0xffffffffu, t0, 1));
        t0 = fmaxf(t0, __shfl_xor_sync(0xffffffffu, t0, 2));
        t1 = fmaxf(t1, __shfl_xor_sync(0xffffffffu, t1, 1));
        t1 = fmaxf(t1, __shfl_xor_sync(0xffffffffu, t1, 2));

        const float mn0 = fmaxf(m0r, t0), mn1 = fmaxf(m1r, t1);
        const float cr0 = ex2((m0r - mn0) * FA_C1);
        const float cr1 = ex2((m1r - mn1) * FA_C1);
        m0r = mn0; m1r = mn1;
        l0 *= cr0; l1 *= cr1;
        #pragma unroll
        for (int d = 0; d < 8; d++) {
            oacc[d][0] *= cr0; oacc[d][1] *= cr0;
            oacc[d][2] *= cr1; oacc[d][3] *= cr1;
        }

        const float mc0 = mn0 * FA_C1, mc1 = mn1 * FA_C1;
        float s0 = 0.f, s1 = 0.f;
        #pragma unroll
        for (int nt = 0; nt < 8; nt++) {
            const float p0 = ex2(fmaf(sacc[nt][0], FA_C1, -mc0));
            const float p1 = ex2(fmaf(sacc[nt][1], FA_C1, -mc0));
            const float p2 = ex2(fmaf(sacc[nt][2], FA_C1, -mc1));
            const float p3 = ex2(fmaf(sacc[nt][3], FA_C1, -mc1));
            s0 += p0 + p1; s1 += p2 + p3;
            sacc[nt][0] = p0; sacc[nt][1] = p1; sacc[nt][2] = p2; sacc[nt][3] = p3;
        }
        s0 += __shfl_xor_sync(0xffffffffu, s0, 1);
        s0 += __shfl_xor_sync(0xffffffffu, s0, 2);
        s1 += __shfl_xor_sync(0xffffffffu, s1, 1);
        s1 += __shfl_xor_sync(0xffffffffu, s1, 2);
        l0 += s0; l1 += s1;

        // ---- O += P V ----
        const int lm = lane >> 3, lr = lane & 7;      // ldmatrix addressing
        #pragma unroll
        for (int j = 0; j < 4; j++) {
            uint32_t a[4];
            a[0] = pack_h2(sacc[2*j  ][0], sacc[2*j  ][1]);
            a[1] = pack_h2(sacc[2*j  ][2], sacc[2*j  ][3]);
            a[2] = pack_h2(sacc[2*j+1][0], sacc[2*j+1][1]);
            a[3] = pack_h2(sacc[2*j+1][2], sacc[2*j+1][3]);
            #pragma unroll
            for (int dtp = 0; dtp < 4; dtp++) {
                const int s_a = j*16 + ((lm & 1) << 3) + lr;
                const int d_a = dtp*16 + ((lm >> 1) << 3);
                const uint32_t addr = vs_b + (uint32_t)(s_a*ALDH + d_a)*2;
                uint32_t b0, b1, b2, b3;
                LDSM_X4_TRANS(b0, b1, b2, b3, addr);
                MMA_F16(oacc[dtp*2],   a, b0, b1);
                MMA_F16(oacc[dtp*2+1], a, b2, b3);
            }
        }
        __syncthreads();

        if (kt + 2 <= qt) load_kv(st, kt + 2);
    }

    // ---- normalize + write (fp16; feeds Wo GEMM) ----
    const float inv0 = 1.0f / l0, inv1 = 1.0f / l1;
    const int r0 = b*SS + qbase + w*16 + gid;
    __half* o0 = O + (size_t)r0*DM + h*DK;
    __half* o1 = o0 + (size_t)8*DM;
    #pragma unroll
    for (int dt = 0; dt < 8; dt++) {
        const int c = dt*8 + 2*tg;
        *(uint32_t*)(o0 + c) = pack_h2(oacc[dt][0]*inv0, oacc[dt][1]*inv0);
        *(uint32_t*)(o1 + c) = pack_h2(oacc[dt][2]*inv1, oacc[dt][3]*inv1);
    }
}

// ---------------------------------------------------------------------------
// Launch
// ---------------------------------------------------------------------------
extern "C" void kernel_launch(void* const* d_in, const int* in_sizes, int n_in,
                              void* d_out, int out_size)
{
    const float* x   = (const float*)d_in[0];
    const float* Wq  = (const float*)d_in[1];
    const float* bq  = (const float*)d_in[2];
    const float* Wk  = (const float*)d_in[3];
    const float* bk  = (const float*)d_in[4];
    const float* Wv  = (const float*)d_in[5];
    const float* bv  = (const float*)d_in[6];
    const float* Wo  = (const float*)d_in[7];
    const float* bo  = (const float*)d_in[8];
    const float* W1  = (const float*)d_in[9];
    const float* b1  = (const float*)d_in[10];
    const float* W2  = (const float*)d_in[11];
    const float* b2  = (const float*)d_in[12];
    const float* g1  = (const float*)d_in[13];
    const float* be1 = (const float*)d_in[14];
    const float* g2  = (const float*)d_in[15];
    const float* be2 = (const float*)d_in[16];
    float* out = (float*)d_out;

    __half *p_h, *p_q, *p_k, *p_v, *p_o, *p_ff;
    __half *p_wqt, *p_wkt, *p_wvt, *p_wot, *p_w1t, *p_w2t;
    float  *p_x1;
    cudaGetSymbolAddress((void**)&p_h,   g_h);
    cudaGetSymbolAddress((void**)&p_q,   g_q);
    cudaGetSymbolAddress((void**)&p_k,   g_k);
    cudaGetSymbolAddress((void**)&p_v,   g_v);
    cudaGetSymbolAddress((void**)&p_o,   g_o);
    cudaGetSymbolAddress((void**)&p_x1,  g_x1);
    cudaGetSymbolAddress((void**)&p_ff,  g_ff);
    cudaGetSymbolAddress((void**)&p_wqt, g_wqt);
    cudaGetSymbolAddress((void**)&p_wkt, g_wkt);
    cudaGetSymbolAddress((void**)&p_wvt, g_wvt);
    cudaGetSymbolAddress((void**)&p_wot, g_wot);
    cudaGetSymbolAddress((void**)&p_w1t, g_w1t);
    cudaGetSymbolAddress((void**)&p_w2t, g_w2t);

    static bool attr_set = false;
    if (!attr_set) {
        cudaFuncSetAttribute(mma_gemm<false,false,true>,
                             cudaFuncAttributeMaxDynamicSharedMemorySize, GEMM_SMEM);
        cudaFuncSetAttribute(mma_gemm<false,true,false>,
                             cudaFuncAttributeMaxDynamicSharedMemorySize, GEMM_SMEM);
        cudaFuncSetAttribute(mma_gemm<true,false,true>,
                             cudaFuncAttributeMaxDynamicSharedMemorySize, GEMM_SMEM);
        cudaFuncSetAttribute(fa_kernel,
                             cudaFuncAttributeMaxDynamicSharedMemorySize, ATT_SMEM);
        attr_set = true;
    }

    const dim3 tblk(32, 8);
    // Weight prep: 4 fused DxD transposes + 2 FFN transposes
    transpose_round4<<<dim3(DM/32, DM/32, 4), tblk>>>(
        Wq, Wk, Wv, Wo, p_wqt, p_wkt, p_wvt, p_wot);
    transpose_round<<<dim3(DFF/32, DM/32),  tblk>>>(W1, p_w1t, DM,  DFF);
    transpose_round<<<dim3(DM/32,  DFF/32), tblk>>>(W2, p_w2t, DFF, DM);

    const dim3 gD (DM/128,  MROWS/128);   // (8, 64)
    const dim3 gF (DFF/128, MROWS/128);   // (32, 64)

    // 1. ln1(x) -> h (fp16)
    ln_kernel<<<MROWS, 256>>>(x, g1, be1, p_h);
    // 2-4. Q/K/V projections (fp16 tensor pipe)
    mma_gemm<false,false,true><<<gD, 256, GEMM_SMEM>>>(p_h, p_wqt, bq, nullptr, p_q, MROWS, DM, DM);
    mma_gemm<false,false,true><<<gD, 256, GEMM_SMEM>>>(p_h, p_wkt, bk, nullptr, p_k, MROWS, DM, DM);
    mma_gemm<false,false,true><<<gD, 256, GEMM_SMEM>>>(p_h, p_wvt, bv, nullptr, p_v, MROWS, DM, DM);
    // 5. causal attention (fp16 flash attention)
    fa_kernel<<<dim3(SS/64, BB*HH), 128, ATT_SMEM>>>(p_q, p_k, p_v, p_o);
    // 6. output projection + residual(x) -> x1 (fp32)
    mma_gemm<false,true,false><<<gD, 256, GEMM_SMEM>>>(p_o, p_wot, bo, x, p_x1, MROWS, DM, DM);
    // 7. ln2(x1) -> h (fp16)
    ln_kernel<<<MROWS, 256>>>(p_x1, g2, be2, p_h);
    // 8. FFN up + ReLU (fp16 out)
    mma_gemm<true,false,true><<<gF, 256, GEMM_SMEM>>>(p_h, p_w1t, b1, nullptr, p_ff, MROWS, DFF, DM);
    // 9. FFN down + residual(x1) -> out (fp32)
    mma_gemm<false,true,false><<<gD, 256, GEMM_SMEM>>>(p_ff, p_w2t, b2, p_x1, out, MROWS, DM, DFF);
}